// round 13
// baseline (speedup 1.0000x reference)
#include <cuda_runtime.h>
#include <cuda_fp16.h>
#include <stdint.h>

// ---------------------------------------------------------------------------
// Problem constants
// ---------------------------------------------------------------------------
#define NTOK 4096          // B*S
#define HDIM 1024          // hidden
#define IDIM 4096          // intermediate
#define TTASK 8            // tasks
#define TD 512             // T*D
#define TDBP 640           // T*D + T, padded to multiple of 128

// ---------------------------------------------------------------------------
// Scratch (static device globals; no allocation allowed)
// ---------------------------------------------------------------------------
__device__ __align__(16) __half g_hsh[NTOK * IDIM];   // hs in fp16
__device__ float  g_h  [NTOK * HDIM];                 // dense out (fp32); later reused for fus
__device__ __align__(16) __half g_hh [NTOK * HDIM];   // h in fp16
__device__ __align__(16) __half g_pre[NTOK * HDIM];
__device__ __align__(16) __half g_ain[NTOK * HDIM];
__device__ __align__(16) __half g_dr [NTOK * TD];
__device__ __align__(16) __half g_e  [NTOK * TD];
__device__ __align__(16) __half g_pdr[NTOK * TDBP];
__device__ float  g_hv [NTOK * HDIM];                 // h @ value_w^T (fp32)
// fp16 weights, all [N, K] row-major
__device__ __align__(16) __half g_dw  [HDIM * IDIM];  // dense_w
__device__ __align__(16) __half g_dnw [TD * HDIM];    // down_w
__device__ __align__(16) __half g_qwT [HDIM * HDIM];  // query_w^T
__device__ __align__(16) __half g_kwN [HDIM * HDIM];  // key_w (plain copy)
__device__ __align__(16) __half g_vw  [HDIM * HDIM];  // value_w
__device__ __align__(16) __half g_uw2e[TDBP * HDIM];  // rows j<512: up_w[t,h,d]; 512..519: up_b; else 0
__device__ __align__(16) __half g_uk  [TD * HDIM];    // UK = uw2 @ Kw^T
__device__ __align__(16) __half g_we  [TD * HDIM];    // We = UK @ Qw
__device__ __align__(16) __half g_w2  [HDIM * TDBP];  // W2 = value_w @ uw2e^T
__device__ float g_qkb[HDIM];                         // query_b @ key_w
__device__ float g_eb [TD];                           // qkb . uw2[j]
__device__ float g_v1 [TTASK * HDIM];                 // up_b @ Kw^T (per task)
__device__ float g_ub2[TTASK * HDIM];                 // v1 @ Qw
__device__ float g_cb [TTASK];                        // qkb . up_b[t]

// ---------------------------------------------------------------------------
// PTX helpers
// ---------------------------------------------------------------------------
__device__ __forceinline__ uint32_t smem_u32(const void* p) {
    uint32_t a;
    asm("{ .reg .u64 t; cvta.to.shared.u64 t, %1; cvt.u32.u64 %0, t; }" : "=r"(a) : "l"(p));
    return a;
}
__device__ __forceinline__ void cp_async16(uint32_t smem, const void* gmem) {
    asm volatile("cp.async.cg.shared.global [%0], [%1], 16;\n" :: "r"(smem), "l"(gmem));
}
__device__ __forceinline__ void cp_commit() {
    asm volatile("cp.async.commit_group;\n");
}
template<int W> __device__ __forceinline__ void cp_wait() {
    asm volatile("cp.async.wait_group %0;\n" :: "n"(W));
}
__device__ __forceinline__ uint32_t sw128(uint32_t off) {   // SW128 swizzle
    return off ^ ((off >> 3) & 0x70);
}
__device__ __forceinline__ void ldsm4(uint32_t* d, uint32_t addr) {
    asm volatile("ldmatrix.sync.aligned.m8n8.x4.shared.b16 {%0,%1,%2,%3}, [%4];"
        : "=r"(d[0]), "=r"(d[1]), "=r"(d[2]), "=r"(d[3]) : "r"(addr));
}
__device__ __forceinline__ void mma_f16(float* c, const uint32_t* a, const uint32_t* b) {
    asm volatile("mma.sync.aligned.m16n8k16.row.col.f32.f16.f16.f32 "
        "{%0,%1,%2,%3}, {%4,%5,%6,%7}, {%8,%9}, {%0,%1,%2,%3};"
        : "+f"(c[0]), "+f"(c[1]), "+f"(c[2]), "+f"(c[3])
        : "r"(a[0]), "r"(a[1]), "r"(a[2]), "r"(a[3]), "r"(b[0]), "r"(b[1]));
}

// ---------------------------------------------------------------------------
// fp16 HMMA GEMM: C[M,N] = A[M,K](fp16) @ B[N,K](fp16)^T (+bias)(relu)(+C2)
// CTA tile MT x 128, BK=64 halfs (128B SW128 rows), 256 thr, 8 warps (2x4),
// 3-stage cp.async, single barrier per K-iter, fp32 accum, 2 CTAs/SM.
// Requires M%MT==0, N%128==0, K%64==0, K/64 >= 3.
// ---------------------------------------------------------------------------
template<int MT, bool HASBIAS, bool RELU, bool ADDC, bool OUTHALF>
__global__ void __launch_bounds__(256, 2) gemm_h(
    const __half* __restrict__ A, const __half* __restrict__ B,
    const float* __restrict__ bias, const float* __restrict__ C2,
    void* __restrict__ Cv, int N, int K)
{
    constexpr int ASTG = MT * 128;              // bytes per A stage
    constexpr int BSTG = 128 * 128;             // bytes per B stage
    constexpr int MI = MT / 32;                 // 16-row m-subtiles per warp
    extern __shared__ __align__(1024) char smem[];
    const uint32_t sb  = smem_u32(smem);
    const uint32_t SA  = sb;
    const uint32_t SBB = sb + 3 * ASTG;

    const int tid = threadIdx.x, w = tid >> 5, lane = tid & 31;
    const int m0 = blockIdx.y * MT, n0 = blockIdx.x * 128;
    const int wm = (w & 1) * (MT / 2), wn = (w >> 1) * 32;
    const int qr = lane >> 2, qc = lane & 3;
    const int nt = K >> 6;

    auto copy_stage = [&](int s, int k0 /*halfs*/) {
        #pragma unroll
        for (int i = 0; i < MT / 32; i++) {
            int g = tid + 256 * i;
            int r = g >> 3, cb = (g & 7) << 4;
            cp_async16(SA + s * ASTG + sw128(r * 128 + cb),
                       A + (size_t)(m0 + r) * K + k0 + (cb >> 1));
        }
        #pragma unroll
        for (int i = 0; i < 4; i++) {
            int g = tid + 256 * i;
            int r = g >> 3, cb = (g & 7) << 4;
            cp_async16(SBB + s * BSTG + sw128(r * 128 + cb),
                       B + (size_t)(n0 + r) * K + k0 + (cb >> 1));
        }
    };

    float acc[MI][4][4];
    #pragma unroll
    for (int mi = 0; mi < MI; mi++)
        #pragma unroll
        for (int nj = 0; nj < 4; nj++)
            #pragma unroll
            for (int r = 0; r < 4; r++) acc[mi][nj][r] = 0.0f;

    copy_stage(0, 0);   cp_commit();
    copy_stage(1, 64);  cp_commit();

    const int a_r  = lane & 15;
    const int a_cb = (lane >> 4) << 4;            // 0 | 16
    const int b_r  = ((lane >> 4) & 1) * 8 + (lane & 7);
    const int b_cb = ((lane >> 3) & 1) << 4;      // 0 | 16

    for (int t = 0; t < nt; t++) {
        cp_wait<1>();
        __syncthreads();

        const int nxt = t + 2;
        if (nxt < nt) copy_stage(nxt % 3, nxt * 64);
        cp_commit();

        const uint32_t aB = SA  + (t % 3) * ASTG;
        const uint32_t bB = SBB + (t % 3) * BSTG;

        #pragma unroll
        for (int kc = 0; kc < 4; kc++) {
            const int kb = kc * 32;               // byte col base (16 halfs)
            uint32_t bf[8];
            #pragma unroll
            for (int h = 0; h < 2; h++) {
                int r = wn + h * 16 + b_r;
                ldsm4(&bf[h * 4], bB + sw128(r * 128 + kb + b_cb));
            }
            #pragma unroll
            for (int mi = 0; mi < MI; mi++) {
                int r = wm + mi * 16 + a_r;
                uint32_t af[4];
                ldsm4(af, aB + sw128(r * 128 + kb + a_cb));
                #pragma unroll
                for (int nj = 0; nj < 4; nj++)
                    mma_f16(acc[mi][nj], af, &bf[nj * 2]);
            }
        }
    }

    // ----- epilogue -----
    float2 bv[4];
    if (HASBIAS) {
        #pragma unroll
        for (int nj = 0; nj < 4; nj++)
            bv[nj] = *(const float2*)&bias[n0 + wn + nj * 8 + qc * 2];
    }
    #pragma unroll
    for (int mi = 0; mi < MI; mi++) {
        const int r0 = m0 + wm + mi * 16 + qr;
        #pragma unroll
        for (int nj = 0; nj < 4; nj++) {
            const int cc = n0 + wn + nj * 8 + qc * 2;
            float2 v0 = make_float2(acc[mi][nj][0], acc[mi][nj][1]);
            float2 v1 = make_float2(acc[mi][nj][2], acc[mi][nj][3]);
            if (HASBIAS) {
                v0.x += bv[nj].x; v0.y += bv[nj].y;
                v1.x += bv[nj].x; v1.y += bv[nj].y;
            }
            if (ADDC) {
                float2 c0 = *(const float2*)&C2[(size_t)r0 * N + cc];
                float2 c1 = *(const float2*)&C2[(size_t)(r0 + 8) * N + cc];
                v0.x += c0.x; v0.y += c0.y;
                v1.x += c1.x; v1.y += c1.y;
            }
            if (RELU) {
                v0.x = fmaxf(v0.x, 0.f); v0.y = fmaxf(v0.y, 0.f);
                v1.x = fmaxf(v1.x, 0.f); v1.y = fmaxf(v1.y, 0.f);
            }
            if (OUTHALF) {
                __half* C = (__half*)Cv;
                *(__half2*)&C[(size_t)r0 * N + cc]       = __floats2half2_rn(v0.x, v0.y);
                *(__half2*)&C[(size_t)(r0 + 8) * N + cc] = __floats2half2_rn(v1.x, v1.y);
            } else {
                float* C = (float*)Cv;
                *(float2*)&C[(size_t)r0 * N + cc]       = v0;
                *(float2*)&C[(size_t)(r0 + 8) * N + cc] = v1;
            }
        }
    }
}

// ---------------------------------------------------------------------------
// Block reduction (256 threads)
// ---------------------------------------------------------------------------
__device__ __forceinline__ float block_sum256(float v)
{
    __shared__ float buf[8];
    int lane = threadIdx.x & 31, wid = threadIdx.x >> 5;
    #pragma unroll
    for (int o = 16; o > 0; o >>= 1) v += __shfl_xor_sync(0xffffffffu, v, o);
    if (lane == 0) buf[wid] = v;
    __syncthreads();
    float r = buf[0] + buf[1] + buf[2] + buf[3] + buf[4] + buf[5] + buf[6] + buf[7];
    __syncthreads();
    return r;
}

// ---------------------------------------------------------------------------
// add + LayerNorm: x = x1 + x2; optionally write fp16 x AND fp16 x2;
// out = LN(x) (fp16|fp32)
// ---------------------------------------------------------------------------
template<bool WRITE_PRE, bool OUTHALF>
__global__ void __launch_bounds__(256) add_ln_kernel(
    const float* __restrict__ x1, const float* __restrict__ x2,
    const float* __restrict__ gamma, const float* __restrict__ beta,
    __half* __restrict__ pre, __half* __restrict__ hh, void* __restrict__ out)
{
    const int n = blockIdx.x;
    const int tid = threadIdx.x;
    const size_t base = (size_t)n * HDIM;

    float4 a = ((const float4*)(x1 + base))[tid];
    float4 c = ((const float4*)(x2 + base))[tid];
    float4 x = make_float4(a.x + c.x, a.y + c.y, a.z + c.z, a.w + c.w);
    if (WRITE_PRE) {
        __half2* p = (__half2*)(pre + base) + tid * 2;
        p[0] = __floats2half2_rn(x.x, x.y);
        p[1] = __floats2half2_rn(x.z, x.w);
        __half2* q = (__half2*)(hh + base) + tid * 2;
        q[0] = __floats2half2_rn(c.x, c.y);
        q[1] = __floats2half2_rn(c.z, c.w);
    }

    float s = x.x + x.y + x.z + x.w;
    s = block_sum256(s);
    const float mu = s * (1.0f / HDIM);

    float d0 = x.x - mu, d1 = x.y - mu, d2 = x.z - mu, d3 = x.w - mu;
    float sq = d0 * d0 + d1 * d1 + d2 * d2 + d3 * d3;
    sq = block_sum256(sq);
    const float rstd = rsqrtf(sq * (1.0f / HDIM) + 1e-12f);

    float4 g4 = ((const float4*)gamma)[tid];
    float4 b4 = ((const float4*)beta)[tid];
    float o0 = d0 * rstd * g4.x + b4.x;
    float o1 = d1 * rstd * g4.y + b4.y;
    float o2 = d2 * rstd * g4.z + b4.z;
    float o3 = d3 * rstd * g4.w + b4.w;
    if (OUTHALF) {
        __half2* p = (__half2*)((__half*)out + base) + tid * 2;
        p[0] = __floats2half2_rn(o0, o1);
        p[1] = __floats2half2_rn(o2, o3);
    } else {
        ((float4*)((float*)out + base))[tid] = make_float4(o0, o1, o2, o3);
    }
}

// ---------------------------------------------------------------------------
// convA: fp16-convert hs and dense_w (float4 vectorized), one launch (stream 0)
// ---------------------------------------------------------------------------
#define CA0 (NTOK * IDIM / 4)
#define CA1 (HDIM * IDIM / 4)
__global__ void convA_kernel(const float* __restrict__ hs, const float* __restrict__ dense_w,
                             __half* __restrict__ hsh, __half* __restrict__ dw)
{
    int i = blockIdx.x * blockDim.x + threadIdx.x;
    const float* src; __half* dst;
    if (i < CA0) { src = hs; dst = hsh; }
    else if (i < CA0 + CA1) { i -= CA0; src = dense_w; dst = dw; }
    else return;
    float4 v = *(const float4*)(src + (size_t)i * 4);
    __half2* o = (__half2*)(dst + (size_t)i * 4);
    o[0] = __floats2half2_rn(v.x, v.y);
    o[1] = __floats2half2_rn(v.z, v.w);
}

// ---------------------------------------------------------------------------
// prepB: remaining weights (side stream). Segments:
//  0: dnw = h(down_w)             [TD*H]
//  1: vw  = h(value_w)            [H*H]
//  2: qwT[n,k] = h(query_w[k,n])  [H*H]
//  3: kwN = h(key_w)              [H*H]
//  4: uw2e[j,h]                   [TDBP*H]
// ---------------------------------------------------------------------------
#define PB0 (TD * HDIM)
#define PB1 (HDIM * HDIM)
#define PB4 (TDBP * HDIM)
#define PB_TOTAL (PB0 + 3 * PB1 + PB4)

__global__ void prepB_kernel(
    const float* __restrict__ down_w, const float* __restrict__ value_w,
    const float* __restrict__ query_w, const float* __restrict__ key_w,
    const float* __restrict__ up_w,   const float* __restrict__ up_b,
    __half* __restrict__ dnw, __half* __restrict__ vw,
    __half* __restrict__ qwT, __half* __restrict__ kwN,
    __half* __restrict__ uw2e)
{
    int idx = blockIdx.x * blockDim.x + threadIdx.x;
    if (idx < PB0) { dnw[idx] = __float2half_rn(down_w[idx]); return; }
    idx -= PB0;
    if (idx < PB1) { vw[idx] = __float2half_rn(value_w[idx]); return; }
    idx -= PB1;
    if (idx < PB1) {
        int n = idx >> 10, k = idx & (HDIM - 1);
        qwT[idx] = __float2half_rn(query_w[(size_t)k * HDIM + n]);
        return;
    }
    idx -= PB1;
    if (idx < PB1) { kwN[idx] = __float2half_rn(key_w[idx]); return; }
    idx -= PB1;
    if (idx < PB4) {
        int j = idx >> 10, h = idx & (HDIM - 1);
        float v = 0.0f;
        if (j < TD) {
            int t = j >> 6, d = j & 63;
            v = up_w[((size_t)t * HDIM + h) * 64 + d];
        } else if (j < TD + TTASK) {
            v = up_b[(size_t)(j - TD) * HDIM + h];
        }
        uw2e[idx] = __float2half_rn(v);
    }
}

// qkb[k] = sum_j query_b[j] * key_w[j,k]
__global__ void qkb_kernel(const float* __restrict__ qb,
                           const float* __restrict__ kw,
                           float* __restrict__ qkb)
{
    int k = blockIdx.x * blockDim.x + threadIdx.x;
    if (k >= HDIM) return;
    float s = 0.f;
    #pragma unroll 8
    for (int j = 0; j < HDIM; j++) s += qb[j] * kw[(size_t)j * HDIM + k];
    qkb[k] = s;
}

// eb[j] = sum_h qkb[h] * uw2e[j,h]
__global__ void eb_kernel(const float* __restrict__ qkb,
                          const __half* __restrict__ uw2e,
                          float* __restrict__ eb)
{
    int j = blockIdx.x * blockDim.x + threadIdx.x;
    if (j >= TD) return;
    const __half* row = uw2e + (size_t)j * HDIM;
    float s = 0.f;
    #pragma unroll 8
    for (int h = 0; h < HDIM; h++) s += qkb[h] * __half2float(row[h]);
    eb[j] = s;
}

// v1[t,l] = sum_k up_b[t,k] * key_w[l,k]
__global__ void ub2a_kernel(const float* __restrict__ up_b,
                            const float* __restrict__ key_w,
                            float* __restrict__ v1)
{
    int idx = blockIdx.x * blockDim.x + threadIdx.x;
    if (idx >= TTASK * HDIM) return;
    int t = idx >> 10, l = idx & (HDIM - 1);
    const float* ub = up_b + (size_t)t * HDIM;
    const float* kr = key_w + (size_t)l * HDIM;
    float s = 0.f;
    #pragma unroll 8
    for (int k = 0; k < HDIM; k++) s += ub[k] * kr[k];
    v1[idx] = s;
}

// ub2[t,i] = sum_l v1[t,l] * query_w[l,i];  cb[t] = sum_h qkb[h]*up_b[t,h]
__global__ void ub2b_kernel(const float* __restrict__ v1,
                            const float* __restrict__ query_w,
                            const float* __restrict__ qkb,
                            const float* __restrict__ up_b,
                            float* __restrict__ ub2, float* __restrict__ cb)
{
    int idx = blockIdx.x * blockDim.x + threadIdx.x;
    if (idx < TTASK) {
        float s = 0.f;
        #pragma unroll 8
        for (int h = 0; h < HDIM; h++) s += qkb[h] * up_b[(size_t)idx * HDIM + h];
        cb[idx] = s;
    }
    if (idx >= TTASK * HDIM) return;
    int t = idx >> 10, i = idx & (HDIM - 1);
    const float* vr = v1 + (size_t)t * HDIM;
    float s = 0.f;
    #pragma unroll 8
    for (int l = 0; l < HDIM; l++) s += vr[l] * query_w[(size_t)l * HDIM + i];
    ub2[idx] = s;
}

// ---------------------------------------------------------------------------
// Scores + softmax over tasks + pdr (fp16, stride TDBP, pad zeroed)
//   s[t] = sum_d dr*e  +  sum_i pre[n,i]*ub2[t,i] + cb[t]
// ---------------------------------------------------------------------------
__global__ void __launch_bounds__(256) score_softmax_kernel(
    const __half* __restrict__ dr, const __half* __restrict__ e,
    const __half* __restrict__ pre, const float* __restrict__ ub2,
    const float* __restrict__ cb, __half* __restrict__ pdr)
{
    const int n = blockIdx.x;
    const int tid = threadIdx.x;
    const int w = tid >> 5, l = tid & 31;

    const size_t b512 = (size_t)n * TD;
    float v = __half2float(dr[b512 + w * 64 + l])      * __half2float(e[b512 + w * 64 + l])
            + __half2float(dr[b512 + w * 64 + 32 + l]) * __half2float(e[b512 + w * 64 + 32 + l]);

    const __half* prow = pre + (size_t)n * HDIM;
    const float* ur = ub2 + (size_t)w * HDIM;
    float u = 0.f;
    #pragma unroll 8
    for (int h = l; h < HDIM; h += 32) u += __half2float(prow[h]) * ur[h];
    v += u;

    #pragma unroll
    for (int o = 16; o > 0; o >>= 1) v += __shfl_xor_sync(0xffffffffu, v, o);

    __shared__ float s[TTASK];
    if (l == 0) s[w] = v + cb[w];
    __syncthreads();

    float mx = s[0];
    #pragma unroll
    for (int t = 1; t < TTASK; t++) mx = fmaxf(mx, s[t]);
    float p[TTASK]; float sum = 0.f;
    #pragma unroll
    for (int t = 0; t < TTASK; t++) { p[t] = __expf(s[t] - mx); sum += p[t]; }
    const float inv = 1.0f / sum;

    const size_t b = (size_t)n * TDBP;
    #pragma unroll
    for (int r = 0; r < 2; r++) {
        int c = tid + r * 256;
        int t = c >> 6;
        pdr[b + c] = __float2half_rn(p[t] * inv * __half2float(dr[b512 + c]));
    }
    if (tid < TTASK) pdr[b + TD + tid] = __float2half_rn(p[tid] * inv);
    if (tid < TDBP - TD - TTASK) pdr[b + TD + TTASK + tid] = __float2half_rn(0.0f);
}

// ---------------------------------------------------------------------------
// Launch
// ---------------------------------------------------------------------------
struct Scratch {
    __half *hsh, *hh, *pre, *ain, *dr, *e, *pdr;
    __half *dw, *dnw, *qwT, *kwN, *vw, *uw2e, *uk, *we, *w2;
    float *h, *hv, *qkb, *eb, *v1, *ub2, *cb;
    cudaStream_t s1;
    cudaEvent_t evFork, evWe, evLN, evS1;
};

static constexpr int SMEM_128 = 3 * 2 * 16384;           // 98304 B
static constexpr int SMEM_64  = 3 * (8192 + 16384);      // 73728 B

static Scratch init_once()
{
    Scratch s;
    cudaGetSymbolAddress((void**)&s.hsh,  g_hsh);
    cudaGetSymbolAddress((void**)&s.hh,   g_hh);
    cudaGetSymbolAddress((void**)&s.pre,  g_pre);
    cudaGetSymbolAddress((void**)&s.ain,  g_ain);
    cudaGetSymbolAddress((void**)&s.dr,   g_dr);
    cudaGetSymbolAddress((void**)&s.e,    g_e);
    cudaGetSymbolAddress((void**)&s.pdr,  g_pdr);
    cudaGetSymbolAddress((void**)&s.dw,   g_dw);
    cudaGetSymbolAddress((void**)&s.dnw,  g_dnw);
    cudaGetSymbolAddress((void**)&s.qwT,  g_qwT);
    cudaGetSymbolAddress((void**)&s.kwN,  g_kwN);
    cudaGetSymbolAddress((void**)&s.vw,   g_vw);
    cudaGetSymbolAddress((void**)&s.uw2e, g_uw2e);
    cudaGetSymbolAddress((void**)&s.uk,   g_uk);
    cudaGetSymbolAddress((void**)&s.we,   g_we);
    cudaGetSymbolAddress((void**)&s.w2,   g_w2);
    cudaGetSymbolAddress((void**)&s.h,    g_h);
    cudaGetSymbolAddress((void**)&s.hv,   g_hv);
    cudaGetSymbolAddress((void**)&s.qkb,  g_qkb);
    cudaGetSymbolAddress((void**)&s.eb,   g_eb);
    cudaGetSymbolAddress((void**)&s.v1,   g_v1);
    cudaGetSymbolAddress((void**)&s.ub2,  g_ub2);
    cudaGetSymbolAddress((void**)&s.cb,   g_cb);
    cudaFuncSetAttribute(gemm_h<128, true,  false, false, false>, cudaFuncAttributeMaxDynamicSharedMemorySize, SMEM_128);
    cudaFuncSetAttribute(gemm_h<128, false, false, false, false>, cudaFuncAttributeMaxDynamicSharedMemorySize, SMEM_128);
    cudaFuncSetAttribute(gemm_h<128, false, false, true,  false>, cudaFuncAttributeMaxDynamicSharedMemorySize, SMEM_128);
    cudaFuncSetAttribute(gemm_h<64,  true,  true,  false, true >, cudaFuncAttributeMaxDynamicSharedMemorySize, SMEM_64);
    cudaFuncSetAttribute(gemm_h<64,  true,  false, false, true >, cudaFuncAttributeMaxDynamicSharedMemorySize, SMEM_64);
    cudaFuncSetAttribute(gemm_h<64,  false, false, false, true >, cudaFuncAttributeMaxDynamicSharedMemorySize, SMEM_64);
    cudaStreamCreateWithFlags(&s.s1, cudaStreamNonBlocking);
    cudaEventCreateWithFlags(&s.evFork, cudaEventDisableTiming);
    cudaEventCreateWithFlags(&s.evWe,   cudaEventDisableTiming);
    cudaEventCreateWithFlags(&s.evLN,   cudaEventDisableTiming);
    cudaEventCreateWithFlags(&s.evS1,   cudaEventDisableTiming);
    return s;
}

extern "C" void kernel_launch(void* const* d_in, const int* in_sizes, int n_in,
                              void* d_out, int out_size)
{
    const float* hs      = (const float*)d_in[0];
    const float* inp     = (const float*)d_in[1];
    const float* dense_w = (const float*)d_in[2];
    const float* dense_b = (const float*)d_in[3];
    const float* ln_g    = (const float*)d_in[4];
    const float* ln_b    = (const float*)d_in[5];
    const float* down_w  = (const float*)d_in[6];
    const float* down_b  = (const float*)d_in[7];
    const float* up_w    = (const float*)d_in[8];
    const float* up_b    = (const float*)d_in[9];
    const float* key_w   = (const float*)d_in[10];  // key_b cancels in softmax
    const float* query_w = (const float*)d_in[12];
    const float* query_b = (const float*)d_in[13];
    const float* value_w = (const float*)d_in[14];
    float* out = (float*)d_out;

    static Scratch s = init_once();
    cudaStream_t s0 = 0, s1 = s.s1;
    dim3 blk(256);

    // ---- fork: s1 branches off s0 ----
    cudaEventRecord(s.evFork, s0);
    cudaStreamWaitEvent(s1, s.evFork, 0);

    // s1: weight prep -> qkb/eb -> UK -> We (then W2 + ub2, off the e path)
    prepB_kernel<<<(PB_TOTAL + 255) / 256, blk, 0, s1>>>(
        down_w, value_w, query_w, key_w, up_w, up_b,
        s.dnw, s.vw, s.qwT, s.kwN, s.uw2e);
    qkb_kernel<<<HDIM / 256, blk, 0, s1>>>(query_b, key_w, s.qkb);
    eb_kernel<<<TD / 256, blk, 0, s1>>>(s.qkb, s.uw2e, s.eb);
    // UK = uw2 @ Kw^T                          [512,1024], K=1024
    gemm_h<64, false, false, false, true><<<dim3(8, 8), blk, SMEM_64, s1>>>(
        s.uw2e, s.kwN, nullptr, nullptr, s.uk, HDIM, HDIM);
    // We = UK @ qwT^T  ( = UK @ Qw )           [512,1024], K=1024
    gemm_h<64, false, false, false, true><<<dim3(8, 8), blk, SMEM_64, s1>>>(
        s.uk, s.qwT, nullptr, nullptr, s.we, HDIM, HDIM);
    cudaEventRecord(s.evWe, s1);
    // W2 = value_w @ uw2e^T                    [1024,640], K=1024
    gemm_h<64, false, false, false, true><<<dim3(TDBP / 128, 16), blk, SMEM_64, s1>>>(
        s.vw, s.uw2e, nullptr, nullptr, s.w2, TDBP, HDIM);
    ub2a_kernel<<<(TTASK * HDIM + 255) / 256, blk, 0, s1>>>(up_b, key_w, s.v1);
    ub2b_kernel<<<(TTASK * HDIM + 255) / 256, blk, 0, s1>>>(
        s.v1, query_w, s.qkb, up_b, s.ub2, s.cb);

    // s0: conversions for the dense GEMM, then dense + LN1
    convA_kernel<<<(CA0 + CA1 + 255) / 256, blk, 0, s0>>>(hs, dense_w, s.hsh, s.dw);
    // h = hs @ dense_w^T + dense_b             [4096,1024], K=4096 (fp32 out)
    gemm_h<128, true, false, false, false><<<dim3(8, 32), blk, SMEM_128, s0>>>(
        s.hsh, s.dw, dense_b, nullptr, s.h, HDIM, IDIM);
    // pre = h16(inp + h); ain = h16(LN(.)); hh = h16(h)
    add_ln_kernel<true, true><<<NTOK, blk, 0, s0>>>(inp, s.h, ln_g, ln_b, s.pre, s.hh, s.ain);
    cudaEventRecord(s.evLN, s0);

    // s1 (after LN): dr-GEMM and hv-GEMM, concurrent with s0's e
    cudaStreamWaitEvent(s1, s.evLN, 0);
    // dr = relu(ain @ down_w^T + down_b)       [4096,512], K=1024
    gemm_h<64, true, true, false, true><<<dim3(4, 64), blk, SMEM_64, s1>>>(
        s.ain, s.dnw, down_b, nullptr, s.dr, TD, HDIM);
    // hv = hh @ value_w^T                      [4096,1024], K=1024 (fp32 out)
    gemm_h<128, false, false, false, false><<<dim3(8, 32), blk, SMEM_128, s1>>>(
        s.hh, s.vw, nullptr, nullptr, s.hv, HDIM, HDIM);
    cudaEventRecord(s.evS1, s1);

    // s0: e -> (join) -> score -> fus -> LN2
    cudaStreamWaitEvent(s0, s.evWe, 0);
    // e = pre @ We^T + eb                      [4096,512], K=1024
    gemm_h<64, true, false, false, true><<<dim3(4, 64), blk, SMEM_64, s0>>>(
        s.pre, s.we, s.eb, nullptr, s.e, TD, HDIM);
    cudaStreamWaitEvent(s0, s.evS1, 0);   // dr/hv done; W2/ub2 precede evS1 on s1
    // scores + softmax + pdr
    score_softmax_kernel<<<NTOK, blk, 0, s0>>>(s.dr, s.e, s.pre, s.ub2, s.cb, s.pdr);
    // fus = pdr @ W2^T + hv                    [4096,1024], K=640 (fp32 out -> g_h)
    gemm_h<128, false, false, true, false><<<dim3(8, 32), blk, SMEM_128, s0>>>(
        s.pdr, s.w2, nullptr, s.hv, s.h, HDIM, TDBP);
    // out = LN(inp + fus)
    add_ln_kernel<false, false><<<NTOK, blk, 0, s0>>>(inp, s.h, ln_g, ln_b, nullptr, nullptr, out);
}

// round 14
// speedup vs baseline: 2.1813x; 2.1813x over previous
#include <cuda_runtime.h>
#include <cuda_fp16.h>
#include <stdint.h>

// ---------------------------------------------------------------------------
// Problem constants
// ---------------------------------------------------------------------------
#define NTOK 4096          // B*S
#define HDIM 1024          // hidden
#define IDIM 4096          // intermediate
#define TTASK 8            // tasks
#define TD 512             // T*D
#define TDBP 640           // T*D + T, padded to multiple of 128

// ---------------------------------------------------------------------------
// Scratch (static device globals; no allocation allowed)
// ---------------------------------------------------------------------------
__device__ __align__(16) __half g_hsh[NTOK * IDIM];   // hs in fp16
__device__ float  g_h  [NTOK * HDIM];                 // dense out (fp32); later reused for fus
__device__ __align__(16) __half g_hh [NTOK * HDIM];   // h in fp16
__device__ __align__(16) __half g_pre[NTOK * HDIM];
__device__ __align__(16) __half g_ain[NTOK * HDIM];
__device__ __align__(16) __half g_dr [NTOK * TD];
__device__ __align__(16) __half g_qk [NTOK * HDIM];
__device__ __align__(16) __half g_e  [NTOK * TD];
__device__ __align__(16) __half g_pdr[NTOK * TDBP];
__device__ float  g_hv [NTOK * HDIM];                 // h @ value_w^T (fp32)
// fp16 weights, all [N, K] row-major
__device__ __align__(16) __half g_dw  [HDIM * IDIM];  // dense_w
__device__ __align__(16) __half g_dnw [TD * HDIM];    // down_w
__device__ __align__(16) __half g_qwT [HDIM * HDIM];  // query_w^T
__device__ __align__(16) __half g_kwT [HDIM * HDIM];  // key_w^T
__device__ __align__(16) __half g_wqk [HDIM * HDIM];  // W_qk = Qw^T Kw
__device__ __align__(16) __half g_vw  [HDIM * HDIM];  // value_w
__device__ __align__(16) __half g_uw2e[TDBP * HDIM];  // rows j<512: up_w[t,h,d]; 512..519: up_b; else 0
__device__ __align__(16) __half g_w2  [HDIM * TDBP];  // W2 = value_w @ uw2e^T  [n][j]
__device__ float g_qkb[HDIM];                         // query_b @ key_w

// ---------------------------------------------------------------------------
// PTX helpers
// ---------------------------------------------------------------------------
__device__ __forceinline__ uint32_t smem_u32(const void* p) {
    uint32_t a;
    asm("{ .reg .u64 t; cvta.to.shared.u64 t, %1; cvt.u32.u64 %0, t; }" : "=r"(a) : "l"(p));
    return a;
}
__device__ __forceinline__ void cp_async16(uint32_t smem, const void* gmem) {
    asm volatile("cp.async.cg.shared.global [%0], [%1], 16;\n" :: "r"(smem), "l"(gmem));
}
__device__ __forceinline__ void cp_commit() {
    asm volatile("cp.async.commit_group;\n");
}
template<int W> __device__ __forceinline__ void cp_wait() {
    asm volatile("cp.async.wait_group %0;\n" :: "n"(W));
}
__device__ __forceinline__ uint32_t sw128(uint32_t off) {   // SW128 swizzle
    return off ^ ((off >> 3) & 0x70);
}
__device__ __forceinline__ void ldsm4(uint32_t* d, uint32_t addr) {
    asm volatile("ldmatrix.sync.aligned.m8n8.x4.shared.b16 {%0,%1,%2,%3}, [%4];"
        : "=r"(d[0]), "=r"(d[1]), "=r"(d[2]), "=r"(d[3]) : "r"(addr));
}
__device__ __forceinline__ void mma_f16(float* c, const uint32_t* a, const uint32_t* b) {
    asm volatile("mma.sync.aligned.m16n8k16.row.col.f32.f16.f16.f32 "
        "{%0,%1,%2,%3}, {%4,%5,%6,%7}, {%8,%9}, {%0,%1,%2,%3};"
        : "+f"(c[0]), "+f"(c[1]), "+f"(c[2]), "+f"(c[3])
        : "r"(a[0]), "r"(a[1]), "r"(a[2]), "r"(a[3]), "r"(b[0]), "r"(b[1]));
}

// ---------------------------------------------------------------------------
// fp16 HMMA GEMM: C[M,N] = A[M,K](fp16) @ B[N,K](fp16)^T (+bias)(relu)(+C2)
// CTA tile MT x 128, BK=64 halfs (128B SW128 rows), 256 thr, 8 warps (2x4),
// 3-stage cp.async, single barrier per K-iter, fp32 accum, 2 CTAs/SM.
// Requires M%MT==0, N%128==0, K%64==0, K/64 >= 3.
// ---------------------------------------------------------------------------
template<int MT, bool HASBIAS, bool RELU, bool ADDC, bool OUTHALF>
__global__ void __launch_bounds__(256, 2) gemm_h(
    const __half* __restrict__ A, const __half* __restrict__ B,
    const float* __restrict__ bias, const float* __restrict__ C2,
    void* __restrict__ Cv, int N, int K)
{
    constexpr int ASTG = MT * 128;              // bytes per A stage
    constexpr int BSTG = 128 * 128;             // bytes per B stage
    constexpr int MI = MT / 32;                 // 16-row m-subtiles per warp
    extern __shared__ __align__(1024) char smem[];
    const uint32_t sb  = smem_u32(smem);
    const uint32_t SA  = sb;
    const uint32_t SBB = sb + 3 * ASTG;

    const int tid = threadIdx.x, w = tid >> 5, lane = tid & 31;
    const int m0 = blockIdx.y * MT, n0 = blockIdx.x * 128;
    const int wm = (w & 1) * (MT / 2), wn = (w >> 1) * 32;
    const int qr = lane >> 2, qc = lane & 3;
    const int nt = K >> 6;

    auto copy_stage = [&](int s, int k0 /*halfs*/) {
        #pragma unroll
        for (int i = 0; i < MT / 32; i++) {
            int g = tid + 256 * i;
            int r = g >> 3, cb = (g & 7) << 4;
            cp_async16(SA + s * ASTG + sw128(r * 128 + cb),
                       A + (size_t)(m0 + r) * K + k0 + (cb >> 1));
        }
        #pragma unroll
        for (int i = 0; i < 4; i++) {
            int g = tid + 256 * i;
            int r = g >> 3, cb = (g & 7) << 4;
            cp_async16(SBB + s * BSTG + sw128(r * 128 + cb),
                       B + (size_t)(n0 + r) * K + k0 + (cb >> 1));
        }
    };

    float acc[MI][4][4];
    #pragma unroll
    for (int mi = 0; mi < MI; mi++)
        #pragma unroll
        for (int nj = 0; nj < 4; nj++)
            #pragma unroll
            for (int r = 0; r < 4; r++) acc[mi][nj][r] = 0.0f;

    copy_stage(0, 0);   cp_commit();
    copy_stage(1, 64);  cp_commit();

    const int a_r  = lane & 15;
    const int a_cb = (lane >> 4) << 4;            // 0 | 16
    const int b_r  = ((lane >> 4) & 1) * 8 + (lane & 7);
    const int b_cb = ((lane >> 3) & 1) << 4;      // 0 | 16

    for (int t = 0; t < nt; t++) {
        cp_wait<1>();
        __syncthreads();

        const int nxt = t + 2;
        if (nxt < nt) copy_stage(nxt % 3, nxt * 64);
        cp_commit();

        const uint32_t aB = SA  + (t % 3) * ASTG;
        const uint32_t bB = SBB + (t % 3) * BSTG;

        #pragma unroll
        for (int kc = 0; kc < 4; kc++) {
            const int kb = kc * 32;               // byte col base (16 halfs)
            uint32_t bf[8];
            #pragma unroll
            for (int h = 0; h < 2; h++) {
                int r = wn + h * 16 + b_r;
                ldsm4(&bf[h * 4], bB + sw128(r * 128 + kb + b_cb));
            }
            #pragma unroll
            for (int mi = 0; mi < MI; mi++) {
                int r = wm + mi * 16 + a_r;
                uint32_t af[4];
                ldsm4(af, aB + sw128(r * 128 + kb + a_cb));
                #pragma unroll
                for (int nj = 0; nj < 4; nj++)
                    mma_f16(acc[mi][nj], af, &bf[nj * 2]);
            }
        }
    }

    // ----- epilogue -----
    float2 bv[4];
    if (HASBIAS) {
        #pragma unroll
        for (int nj = 0; nj < 4; nj++)
            bv[nj] = *(const float2*)&bias[n0 + wn + nj * 8 + qc * 2];
    }
    #pragma unroll
    for (int mi = 0; mi < MI; mi++) {
        const int r0 = m0 + wm + mi * 16 + qr;
        #pragma unroll
        for (int nj = 0; nj < 4; nj++) {
            const int cc = n0 + wn + nj * 8 + qc * 2;
            float2 v0 = make_float2(acc[mi][nj][0], acc[mi][nj][1]);
            float2 v1 = make_float2(acc[mi][nj][2], acc[mi][nj][3]);
            if (HASBIAS) {
                v0.x += bv[nj].x; v0.y += bv[nj].y;
                v1.x += bv[nj].x; v1.y += bv[nj].y;
            }
            if (ADDC) {
                float2 c0 = *(const float2*)&C2[(size_t)r0 * N + cc];
                float2 c1 = *(const float2*)&C2[(size_t)(r0 + 8) * N + cc];
                v0.x += c0.x; v0.y += c0.y;
                v1.x += c1.x; v1.y += c1.y;
            }
            if (RELU) {
                v0.x = fmaxf(v0.x, 0.f); v0.y = fmaxf(v0.y, 0.f);
                v1.x = fmaxf(v1.x, 0.f); v1.y = fmaxf(v1.y, 0.f);
            }
            if (OUTHALF) {
                __half* C = (__half*)Cv;
                *(__half2*)&C[(size_t)r0 * N + cc]       = __floats2half2_rn(v0.x, v0.y);
                *(__half2*)&C[(size_t)(r0 + 8) * N + cc] = __floats2half2_rn(v1.x, v1.y);
            } else {
                float* C = (float*)Cv;
                *(float2*)&C[(size_t)r0 * N + cc]       = v0;
                *(float2*)&C[(size_t)(r0 + 8) * N + cc] = v1;
            }
        }
    }
}

// ---------------------------------------------------------------------------
// Block reduction (256 threads)
// ---------------------------------------------------------------------------
__device__ __forceinline__ float block_sum256(float v)
{
    __shared__ float buf[8];
    int lane = threadIdx.x & 31, wid = threadIdx.x >> 5;
    #pragma unroll
    for (int o = 16; o > 0; o >>= 1) v += __shfl_xor_sync(0xffffffffu, v, o);
    if (lane == 0) buf[wid] = v;
    __syncthreads();
    float r = buf[0] + buf[1] + buf[2] + buf[3] + buf[4] + buf[5] + buf[6] + buf[7];
    __syncthreads();
    return r;
}

// ---------------------------------------------------------------------------
// add + LayerNorm: x = x1 + x2; optionally write fp16 x AND fp16 x2;
// out = LN(x) (fp16|fp32)
// ---------------------------------------------------------------------------
template<bool WRITE_PRE, bool OUTHALF>
__global__ void __launch_bounds__(256) add_ln_kernel(
    const float* __restrict__ x1, const float* __restrict__ x2,
    const float* __restrict__ gamma, const float* __restrict__ beta,
    __half* __restrict__ pre, __half* __restrict__ hh, void* __restrict__ out)
{
    const int n = blockIdx.x;
    const int tid = threadIdx.x;
    const size_t base = (size_t)n * HDIM;

    float4 a = ((const float4*)(x1 + base))[tid];
    float4 c = ((const float4*)(x2 + base))[tid];
    float4 x = make_float4(a.x + c.x, a.y + c.y, a.z + c.z, a.w + c.w);
    if (WRITE_PRE) {
        __half2* p = (__half2*)(pre + base) + tid * 2;
        p[0] = __floats2half2_rn(x.x, x.y);
        p[1] = __floats2half2_rn(x.z, x.w);
        __half2* q = (__half2*)(hh + base) + tid * 2;
        q[0] = __floats2half2_rn(c.x, c.y);
        q[1] = __floats2half2_rn(c.z, c.w);
    }

    float s = x.x + x.y + x.z + x.w;
    s = block_sum256(s);
    const float mu = s * (1.0f / HDIM);

    float d0 = x.x - mu, d1 = x.y - mu, d2 = x.z - mu, d3 = x.w - mu;
    float sq = d0 * d0 + d1 * d1 + d2 * d2 + d3 * d3;
    sq = block_sum256(sq);
    const float rstd = rsqrtf(sq * (1.0f / HDIM) + 1e-12f);

    float4 g4 = ((const float4*)gamma)[tid];
    float4 b4 = ((const float4*)beta)[tid];
    float o0 = d0 * rstd * g4.x + b4.x;
    float o1 = d1 * rstd * g4.y + b4.y;
    float o2 = d2 * rstd * g4.z + b4.z;
    float o3 = d3 * rstd * g4.w + b4.w;
    if (OUTHALF) {
        __half2* p = (__half2*)((__half*)out + base) + tid * 2;
        p[0] = __floats2half2_rn(o0, o1);
        p[1] = __floats2half2_rn(o2, o3);
    } else {
        ((float4*)((float*)out + base))[tid] = make_float4(o0, o1, o2, o3);
    }
}

// ---------------------------------------------------------------------------
// convA: fp16-convert hs and dense_w (float4 vectorized), one launch (stream 0)
// ---------------------------------------------------------------------------
#define CA0 (NTOK * IDIM / 4)
#define CA1 (HDIM * IDIM / 4)
__global__ void convA_kernel(const float* __restrict__ hs, const float* __restrict__ dense_w,
                             __half* __restrict__ hsh, __half* __restrict__ dw)
{
    int i = blockIdx.x * blockDim.x + threadIdx.x;
    const float* src; __half* dst;
    if (i < CA0) { src = hs; dst = hsh; }
    else if (i < CA0 + CA1) { i -= CA0; src = dense_w; dst = dw; }
    else return;
    float4 v = *(const float4*)(src + (size_t)i * 4);
    __half2* o = (__half2*)(dst + (size_t)i * 4);
    o[0] = __floats2half2_rn(v.x, v.y);
    o[1] = __floats2half2_rn(v.z, v.w);
}

// ---------------------------------------------------------------------------
// prepB: remaining weights (side stream). Segments:
//  0: dnw = h(down_w)             [TD*H]
//  1: vw  = h(value_w)            [H*H]
//  2: qwT[n,k] = h(query_w[k,n])  [H*H]
//  3: kwT[n,k] = h(key_w[k,n])    [H*H]
//  4: uw2e[j,h]                   [TDBP*H]
// ---------------------------------------------------------------------------
#define PB0 (TD * HDIM)
#define PB1 (HDIM * HDIM)
#define PB4 (TDBP * HDIM)
#define PB_TOTAL (PB0 + 3 * PB1 + PB4)

__global__ void prepB_kernel(
    const float* __restrict__ down_w, const float* __restrict__ value_w,
    const float* __restrict__ query_w, const float* __restrict__ key_w,
    const float* __restrict__ up_w,   const float* __restrict__ up_b,
    __half* __restrict__ dnw, __half* __restrict__ vw,
    __half* __restrict__ qwT, __half* __restrict__ kwT,
    __half* __restrict__ uw2e)
{
    int idx = blockIdx.x * blockDim.x + threadIdx.x;
    if (idx < PB0) { dnw[idx] = __float2half_rn(down_w[idx]); return; }
    idx -= PB0;
    if (idx < PB1) { vw[idx] = __float2half_rn(value_w[idx]); return; }
    idx -= PB1;
    if (idx < PB1) {
        int n = idx >> 10, k = idx & (HDIM - 1);
        qwT[idx] = __float2half_rn(query_w[(size_t)k * HDIM + n]);
        return;
    }
    idx -= PB1;
    if (idx < PB1) {
        int n = idx >> 10, k = idx & (HDIM - 1);
        kwT[idx] = __float2half_rn(key_w[(size_t)k * HDIM + n]);
        return;
    }
    idx -= PB1;
    if (idx < PB4) {
        int j = idx >> 10, h = idx & (HDIM - 1);
        float v = 0.0f;
        if (j < TD) {
            int t = j >> 6, d = j & 63;
            v = up_w[((size_t)t * HDIM + h) * 64 + d];
        } else if (j < TD + TTASK) {
            v = up_b[(size_t)(j - TD) * HDIM + h];
        }
        uw2e[idx] = __float2half_rn(v);
    }
}

// qkb[k] = sum_j query_b[j] * key_w[j,k]
__global__ void qkb_kernel(const float* __restrict__ qb,
                           const float* __restrict__ kw,
                           float* __restrict__ qkb)
{
    int k = blockIdx.x * blockDim.x + threadIdx.x;
    if (k >= HDIM) return;
    float s = 0.f;
    #pragma unroll 8
    for (int j = 0; j < HDIM; j++) s += qb[j] * kw[(size_t)j * HDIM + k];
    qkb[k] = s;
}

// ---------------------------------------------------------------------------
// Scores + softmax over tasks + pdr (fp16, stride TDBP, pad zeroed)
// ---------------------------------------------------------------------------
__global__ void __launch_bounds__(256) score_softmax_kernel(
    const __half* __restrict__ dr, const __half* __restrict__ e,
    const __half* __restrict__ qk, const float* __restrict__ up_b,
    __half* __restrict__ pdr)
{
    const int n = blockIdx.x;
    const int tid = threadIdx.x;
    const int w = tid >> 5, l = tid & 31;

    const size_t b512 = (size_t)n * TD;
    float v = __half2float(dr[b512 + w * 64 + l])      * __half2float(e[b512 + w * 64 + l])
            + __half2float(dr[b512 + w * 64 + 32 + l]) * __half2float(e[b512 + w * 64 + 32 + l]);

    const __half* qrow = qk + (size_t)n * HDIM;
    const float* ub = up_b + (size_t)w * HDIM;
    float u = 0.f;
    #pragma unroll 8
    for (int h = l; h < HDIM; h += 32) u += __half2float(qrow[h]) * ub[h];
    v += u;

    #pragma unroll
    for (int o = 16; o > 0; o >>= 1) v += __shfl_xor_sync(0xffffffffu, v, o);

    __shared__ float s[TTASK];
    if (l == 0) s[w] = v;
    __syncthreads();

    float mx = s[0];
    #pragma unroll
    for (int t = 1; t < TTASK; t++) mx = fmaxf(mx, s[t]);
    float p[TTASK]; float sum = 0.f;
    #pragma unroll
    for (int t = 0; t < TTASK; t++) { p[t] = __expf(s[t] - mx); sum += p[t]; }
    const float inv = 1.0f / sum;

    const size_t b = (size_t)n * TDBP;
    #pragma unroll
    for (int r = 0; r < 2; r++) {
        int c = tid + r * 256;
        int t = c >> 6;
        pdr[b + c] = __float2half_rn(p[t] * inv * __half2float(dr[b512 + c]));
    }
    if (tid < TTASK) pdr[b + TD + tid] = __float2half_rn(p[tid] * inv);
    if (tid < TDBP - TD - TTASK) pdr[b + TD + TTASK + tid] = __float2half_rn(0.0f);
}

// ---------------------------------------------------------------------------
// Launch
// ---------------------------------------------------------------------------
struct Scratch {
    __half *hsh, *hh, *pre, *ain, *dr, *qk, *e, *pdr;
    __half *dw, *dnw, *qwT, *kwT, *wqk, *vw, *uw2e, *w2;
    float *h, *hv, *qkb;
    cudaStream_t s1;
    cudaEvent_t evFork, evWqk, evLN, evS1;
};

static constexpr int SMEM_128 = 3 * 2 * 16384;           // 98304 B
static constexpr int SMEM_64  = 3 * (8192 + 16384);      // 73728 B

static Scratch init_once()
{
    Scratch s;
    cudaGetSymbolAddress((void**)&s.hsh,  g_hsh);
    cudaGetSymbolAddress((void**)&s.hh,   g_hh);
    cudaGetSymbolAddress((void**)&s.pre,  g_pre);
    cudaGetSymbolAddress((void**)&s.ain,  g_ain);
    cudaGetSymbolAddress((void**)&s.dr,   g_dr);
    cudaGetSymbolAddress((void**)&s.qk,   g_qk);
    cudaGetSymbolAddress((void**)&s.e,    g_e);
    cudaGetSymbolAddress((void**)&s.pdr,  g_pdr);
    cudaGetSymbolAddress((void**)&s.dw,   g_dw);
    cudaGetSymbolAddress((void**)&s.dnw,  g_dnw);
    cudaGetSymbolAddress((void**)&s.qwT,  g_qwT);
    cudaGetSymbolAddress((void**)&s.kwT,  g_kwT);
    cudaGetSymbolAddress((void**)&s.wqk,  g_wqk);
    cudaGetSymbolAddress((void**)&s.vw,   g_vw);
    cudaGetSymbolAddress((void**)&s.uw2e, g_uw2e);
    cudaGetSymbolAddress((void**)&s.w2,   g_w2);
    cudaGetSymbolAddress((void**)&s.h,    g_h);
    cudaGetSymbolAddress((void**)&s.hv,   g_hv);
    cudaGetSymbolAddress((void**)&s.qkb,  g_qkb);
    cudaFuncSetAttribute(gemm_h<128, true,  false, false, false>, cudaFuncAttributeMaxDynamicSharedMemorySize, SMEM_128);
    cudaFuncSetAttribute(gemm_h<128, true,  false, false, true >, cudaFuncAttributeMaxDynamicSharedMemorySize, SMEM_128);
    cudaFuncSetAttribute(gemm_h<128, false, false, false, false>, cudaFuncAttributeMaxDynamicSharedMemorySize, SMEM_128);
    cudaFuncSetAttribute(gemm_h<128, false, false, true,  false>, cudaFuncAttributeMaxDynamicSharedMemorySize, SMEM_128);
    cudaFuncSetAttribute(gemm_h<64,  true,  true,  false, true >, cudaFuncAttributeMaxDynamicSharedMemorySize, SMEM_64);
    cudaFuncSetAttribute(gemm_h<64,  false, false, false, true >, cudaFuncAttributeMaxDynamicSharedMemorySize, SMEM_64);
    cudaStreamCreateWithFlags(&s.s1, cudaStreamNonBlocking);
    cudaEventCreateWithFlags(&s.evFork, cudaEventDisableTiming);
    cudaEventCreateWithFlags(&s.evWqk,  cudaEventDisableTiming);
    cudaEventCreateWithFlags(&s.evLN,   cudaEventDisableTiming);
    cudaEventCreateWithFlags(&s.evS1,   cudaEventDisableTiming);
    return s;
}

extern "C" void kernel_launch(void* const* d_in, const int* in_sizes, int n_in,
                              void* d_out, int out_size)
{
    const float* hs      = (const float*)d_in[0];
    const float* inp     = (const float*)d_in[1];
    const float* dense_w = (const float*)d_in[2];
    const float* dense_b = (const float*)d_in[3];
    const float* ln_g    = (const float*)d_in[4];
    const float* ln_b    = (const float*)d_in[5];
    const float* down_w  = (const float*)d_in[6];
    const float* down_b  = (const float*)d_in[7];
    const float* up_w    = (const float*)d_in[8];
    const float* up_b    = (const float*)d_in[9];
    const float* key_w   = (const float*)d_in[10];  // key_b cancels in softmax
    const float* query_w = (const float*)d_in[12];
    const float* query_b = (const float*)d_in[13];
    const float* value_w = (const float*)d_in[14];
    float* out = (float*)d_out;

    static Scratch s = init_once();
    cudaStream_t s0 = 0, s1 = s.s1;
    dim3 blk(256);

    // ---- fork: s1 branches off s0 ----
    cudaEventRecord(s.evFork, s0);
    cudaStreamWaitEvent(s1, s.evFork, 0);

    // s1: weight prep -> qkb -> wqk -> W2
    prepB_kernel<<<(PB_TOTAL + 255) / 256, blk, 0, s1>>>(
        down_w, value_w, query_w, key_w, up_w, up_b,
        s.dnw, s.vw, s.qwT, s.kwT, s.uw2e);
    qkb_kernel<<<HDIM / 256, blk, 0, s1>>>(query_b, key_w, s.qkb);
    // W_qk[k,i] = sum_j Kw[j,k] Qw[j,i]  (= kwT @ qwT^T)   [1024,1024], K=1024
    gemm_h<64, false, false, false, true><<<dim3(8, 16), blk, SMEM_64, s1>>>(
        s.kwT, s.qwT, nullptr, nullptr, s.wqk, HDIM, HDIM);
    cudaEventRecord(s.evWqk, s1);
    // W2 = value_w @ uw2e^T   [1024, 640], K=1024
    gemm_h<64, false, false, false, true><<<dim3(TDBP / 128, 16), blk, SMEM_64, s1>>>(
        s.vw, s.uw2e, nullptr, nullptr, s.w2, TDBP, HDIM);

    // s0: conversions for the dense GEMM, then dense + LN1
    convA_kernel<<<(CA0 + CA1 + 255) / 256, blk, 0, s0>>>(hs, dense_w, s.hsh, s.dw);
    // h = hs @ dense_w^T + dense_b            [4096,1024], K=4096 (fp32 out)
    gemm_h<128, true, false, false, false><<<dim3(8, 32), blk, SMEM_128, s0>>>(
        s.hsh, s.dw, dense_b, nullptr, s.h, HDIM, IDIM);
    // pre = h16(inp + h); ain = h16(LN(.)); hh = h16(h)
    add_ln_kernel<true, true><<<NTOK, blk, 0, s0>>>(inp, s.h, ln_g, ln_b, s.pre, s.hh, s.ain);
    cudaEventRecord(s.evLN, s0);

    // s1 (after LN): dr-GEMM and hv-GEMM, concurrent with s0's qk/e
    cudaStreamWaitEvent(s1, s.evLN, 0);
    // dr = relu(ain @ down_w^T + down_b)      [4096,512], K=1024
    gemm_h<64, true, true, false, true><<<dim3(4, 64), blk, SMEM_64, s1>>>(
        s.ain, s.dnw, down_b, nullptr, s.dr, TD, HDIM);
    // hv = hh @ value_w^T                     [4096,1024], K=1024 (fp32 out)
    gemm_h<128, false, false, false, false><<<dim3(8, 32), blk, SMEM_128, s1>>>(
        s.hh, s.vw, nullptr, nullptr, s.hv, HDIM, HDIM);
    cudaEventRecord(s.evS1, s1);

    // s0: qk -> e -> (join) -> score -> fus -> LN2
    cudaStreamWaitEvent(s0, s.evWqk, 0);
    // qk = pre @ W_qk^T + qkb                 [4096,1024], K=1024
    gemm_h<128, true, false, false, true><<<dim3(8, 32), blk, SMEM_128, s0>>>(
        s.pre, s.wqk, s.qkb, nullptr, s.qk, HDIM, HDIM);
    // e = qk @ uw2e[0:512]^T                  [4096,512], K=1024
    gemm_h<64, false, false, false, true><<<dim3(4, 64), blk, SMEM_64, s0>>>(
        s.qk, s.uw2e, nullptr, nullptr, s.e, TD, HDIM);
    cudaStreamWaitEvent(s0, s.evS1, 0);
    // scores + softmax + pdr
    score_softmax_kernel<<<NTOK, blk, 0, s0>>>(s.dr, s.e, s.qk, up_b, s.pdr);
    // fus = pdr @ W2^T + hv                   [4096,1024], K=640 (fp32 out -> g_h)
    gemm_h<128, false, false, true, false><<<dim3(8, 32), blk, SMEM_128, s0>>>(
        s.pdr, s.w2, nullptr, s.hv, s.h, HDIM, TDBP);
    // out = LN(inp + fus)
    add_ln_kernel<false, false><<<NTOK, blk, 0, s0>>>(inp, s.h, ln_g, ln_b, nullptr, nullptr, out);
}

// round 15
// speedup vs baseline: 2.1837x; 1.0011x over previous
#include <cuda_runtime.h>
#include <cuda_fp16.h>
#include <stdint.h>

// ---------------------------------------------------------------------------
// Problem constants
// ---------------------------------------------------------------------------
#define NTOK 4096          // B*S
#define HDIM 1024          // hidden
#define IDIM 4096          // intermediate
#define TTASK 8            // tasks
#define TD 512             // T*D
#define TDBP 640           // T*D + T, padded to multiple of 128

// ---------------------------------------------------------------------------
// Scratch (static device globals; no allocation allowed)
// ---------------------------------------------------------------------------
__device__ __align__(16) __half g_hsh[NTOK * IDIM];   // hs in fp16
__device__ float  g_h  [NTOK * HDIM];                 // dense out (fp32); later reused for fus
__device__ __align__(16) __half g_hh [NTOK * HDIM];   // h in fp16
__device__ __align__(16) __half g_pre[NTOK * HDIM];
__device__ __align__(16) __half g_ain[NTOK * HDIM];
__device__ __align__(16) __half g_dr [NTOK * TD];
__device__ __align__(16) __half g_qk [NTOK * HDIM];
__device__ __align__(16) __half g_e  [NTOK * TD];
__device__ __align__(16) __half g_pdr[NTOK * TDBP];
__device__ float  g_hv [NTOK * HDIM];                 // h @ value_w^T (fp32)
// fp16 weights, all [N, K] row-major
__device__ __align__(16) __half g_dw  [HDIM * IDIM];  // dense_w
__device__ __align__(16) __half g_dnw [TD * HDIM];    // down_w
__device__ __align__(16) __half g_qwT [HDIM * HDIM];  // query_w^T
__device__ __align__(16) __half g_kwT [HDIM * HDIM];  // key_w^T
__device__ __align__(16) __half g_wqk [HDIM * HDIM];  // W_qk = Qw^T Kw
__device__ __align__(16) __half g_vw  [HDIM * HDIM];  // value_w
__device__ __align__(16) __half g_uw2e[TDBP * HDIM];  // rows j<512: up_w[t,h,d]; 512..519: up_b; else 0
__device__ __align__(16) __half g_w2  [HDIM * TDBP];  // W2 = value_w @ uw2e^T  [n][j]
__device__ float g_qkb[HDIM];                         // query_b @ key_w

// ---------------------------------------------------------------------------
// PTX helpers
// ---------------------------------------------------------------------------
__device__ __forceinline__ uint32_t smem_u32(const void* p) {
    uint32_t a;
    asm("{ .reg .u64 t; cvta.to.shared.u64 t, %1; cvt.u32.u64 %0, t; }" : "=r"(a) : "l"(p));
    return a;
}
__device__ __forceinline__ void cp_async16(uint32_t smem, const void* gmem) {
    asm volatile("cp.async.cg.shared.global [%0], [%1], 16;\n" :: "r"(smem), "l"(gmem));
}
__device__ __forceinline__ void cp_commit() {
    asm volatile("cp.async.commit_group;\n");
}
template<int W> __device__ __forceinline__ void cp_wait() {
    asm volatile("cp.async.wait_group %0;\n" :: "n"(W));
}
__device__ __forceinline__ uint32_t sw128(uint32_t off) {   // SW128 swizzle
    return off ^ ((off >> 3) & 0x70);
}
__device__ __forceinline__ void ldsm4(uint32_t* d, uint32_t addr) {
    asm volatile("ldmatrix.sync.aligned.m8n8.x4.shared.b16 {%0,%1,%2,%3}, [%4];"
        : "=r"(d[0]), "=r"(d[1]), "=r"(d[2]), "=r"(d[3]) : "r"(addr));
}
__device__ __forceinline__ void mma_f16(float* c, const uint32_t* a, const uint32_t* b) {
    asm volatile("mma.sync.aligned.m16n8k16.row.col.f32.f16.f16.f32 "
        "{%0,%1,%2,%3}, {%4,%5,%6,%7}, {%8,%9}, {%0,%1,%2,%3};"
        : "+f"(c[0]), "+f"(c[1]), "+f"(c[2]), "+f"(c[3])
        : "r"(a[0]), "r"(a[1]), "r"(a[2]), "r"(a[3]), "r"(b[0]), "r"(b[1]));
}

// ---------------------------------------------------------------------------
// fp16 HMMA GEMM: C[M,N] = A[M,K](fp16) @ B[N,K](fp16)^T (+bias)(relu)(+C2)
// CTA tile MT x 128, BK=64 halfs (128B SW128 rows), 256 thr, 8 warps (2x4),
// 3-stage cp.async, single barrier per K-iter, fp32 accum, 2 CTAs/SM.
// Requires M%MT==0, N%128==0, K%64==0, K/64 >= 3.
// ---------------------------------------------------------------------------
template<int MT, bool HASBIAS, bool RELU, bool ADDC, bool OUTHALF>
__global__ void __launch_bounds__(256, 2) gemm_h(
    const __half* __restrict__ A, const __half* __restrict__ B,
    const float* __restrict__ bias, const float* __restrict__ C2,
    void* __restrict__ Cv, int N, int K)
{
    constexpr int ASTG = MT * 128;              // bytes per A stage
    constexpr int BSTG = 128 * 128;             // bytes per B stage
    constexpr int MI = MT / 32;                 // 16-row m-subtiles per warp
    extern __shared__ __align__(1024) char smem[];
    const uint32_t sb  = smem_u32(smem);
    const uint32_t SA  = sb;
    const uint32_t SBB = sb + 3 * ASTG;

    const int tid = threadIdx.x, w = tid >> 5, lane = tid & 31;
    const int m0 = blockIdx.y * MT, n0 = blockIdx.x * 128;
    const int wm = (w & 1) * (MT / 2), wn = (w >> 1) * 32;
    const int qr = lane >> 2, qc = lane & 3;
    const int nt = K >> 6;

    auto copy_stage = [&](int s, int k0 /*halfs*/) {
        #pragma unroll
        for (int i = 0; i < MT / 32; i++) {
            int g = tid + 256 * i;
            int r = g >> 3, cb = (g & 7) << 4;
            cp_async16(SA + s * ASTG + sw128(r * 128 + cb),
                       A + (size_t)(m0 + r) * K + k0 + (cb >> 1));
        }
        #pragma unroll
        for (int i = 0; i < 4; i++) {
            int g = tid + 256 * i;
            int r = g >> 3, cb = (g & 7) << 4;
            cp_async16(SBB + s * BSTG + sw128(r * 128 + cb),
                       B + (size_t)(n0 + r) * K + k0 + (cb >> 1));
        }
    };

    float acc[MI][4][4];
    #pragma unroll
    for (int mi = 0; mi < MI; mi++)
        #pragma unroll
        for (int nj = 0; nj < 4; nj++)
            #pragma unroll
            for (int r = 0; r < 4; r++) acc[mi][nj][r] = 0.0f;

    copy_stage(0, 0);   cp_commit();
    copy_stage(1, 64);  cp_commit();

    const int a_r  = lane & 15;
    const int a_cb = (lane >> 4) << 4;            // 0 | 16
    const int b_r  = ((lane >> 4) & 1) * 8 + (lane & 7);
    const int b_cb = ((lane >> 3) & 1) << 4;      // 0 | 16

    for (int t = 0; t < nt; t++) {
        cp_wait<1>();
        __syncthreads();

        const int nxt = t + 2;
        if (nxt < nt) copy_stage(nxt % 3, nxt * 64);
        cp_commit();

        const uint32_t aB = SA  + (t % 3) * ASTG;
        const uint32_t bB = SBB + (t % 3) * BSTG;

        #pragma unroll
        for (int kc = 0; kc < 4; kc++) {
            const int kb = kc * 32;               // byte col base (16 halfs)
            uint32_t bf[8];
            #pragma unroll
            for (int h = 0; h < 2; h++) {
                int r = wn + h * 16 + b_r;
                ldsm4(&bf[h * 4], bB + sw128(r * 128 + kb + b_cb));
            }
            #pragma unroll
            for (int mi = 0; mi < MI; mi++) {
                int r = wm + mi * 16 + a_r;
                uint32_t af[4];
                ldsm4(af, aB + sw128(r * 128 + kb + a_cb));
                #pragma unroll
                for (int nj = 0; nj < 4; nj++)
                    mma_f16(acc[mi][nj], af, &bf[nj * 2]);
            }
        }
    }

    // ----- epilogue -----
    float2 bv[4];
    if (HASBIAS) {
        #pragma unroll
        for (int nj = 0; nj < 4; nj++)
            bv[nj] = *(const float2*)&bias[n0 + wn + nj * 8 + qc * 2];
    }
    #pragma unroll
    for (int mi = 0; mi < MI; mi++) {
        const int r0 = m0 + wm + mi * 16 + qr;
        #pragma unroll
        for (int nj = 0; nj < 4; nj++) {
            const int cc = n0 + wn + nj * 8 + qc * 2;
            float2 v0 = make_float2(acc[mi][nj][0], acc[mi][nj][1]);
            float2 v1 = make_float2(acc[mi][nj][2], acc[mi][nj][3]);
            if (HASBIAS) {
                v0.x += bv[nj].x; v0.y += bv[nj].y;
                v1.x += bv[nj].x; v1.y += bv[nj].y;
            }
            if (ADDC) {
                float2 c0 = *(const float2*)&C2[(size_t)r0 * N + cc];
                float2 c1 = *(const float2*)&C2[(size_t)(r0 + 8) * N + cc];
                v0.x += c0.x; v0.y += c0.y;
                v1.x += c1.x; v1.y += c1.y;
            }
            if (RELU) {
                v0.x = fmaxf(v0.x, 0.f); v0.y = fmaxf(v0.y, 0.f);
                v1.x = fmaxf(v1.x, 0.f); v1.y = fmaxf(v1.y, 0.f);
            }
            if (OUTHALF) {
                __half* C = (__half*)Cv;
                *(__half2*)&C[(size_t)r0 * N + cc]       = __floats2half2_rn(v0.x, v0.y);
                *(__half2*)&C[(size_t)(r0 + 8) * N + cc] = __floats2half2_rn(v1.x, v1.y);
            } else {
                float* C = (float*)Cv;
                *(float2*)&C[(size_t)r0 * N + cc]       = v0;
                *(float2*)&C[(size_t)(r0 + 8) * N + cc] = v1;
            }
        }
    }
}

// ---------------------------------------------------------------------------
// Block reduction (256 threads)
// ---------------------------------------------------------------------------
__device__ __forceinline__ float block_sum256(float v)
{
    __shared__ float buf[8];
    int lane = threadIdx.x & 31, wid = threadIdx.x >> 5;
    #pragma unroll
    for (int o = 16; o > 0; o >>= 1) v += __shfl_xor_sync(0xffffffffu, v, o);
    if (lane == 0) buf[wid] = v;
    __syncthreads();
    float r = buf[0] + buf[1] + buf[2] + buf[3] + buf[4] + buf[5] + buf[6] + buf[7];
    __syncthreads();
    return r;
}

// ---------------------------------------------------------------------------
// add + LayerNorm: x = x1 + x2; optionally write fp16 x AND fp16 x2;
// out = LN(x) (fp16|fp32)
// ---------------------------------------------------------------------------
template<bool WRITE_PRE, bool OUTHALF>
__global__ void __launch_bounds__(256) add_ln_kernel(
    const float* __restrict__ x1, const float* __restrict__ x2,
    const float* __restrict__ gamma, const float* __restrict__ beta,
    __half* __restrict__ pre, __half* __restrict__ hh, void* __restrict__ out)
{
    const int n = blockIdx.x;
    const int tid = threadIdx.x;
    const size_t base = (size_t)n * HDIM;

    float4 a = ((const float4*)(x1 + base))[tid];
    float4 c = ((const float4*)(x2 + base))[tid];
    float4 x = make_float4(a.x + c.x, a.y + c.y, a.z + c.z, a.w + c.w);
    if (WRITE_PRE) {
        __half2* p = (__half2*)(pre + base) + tid * 2;
        p[0] = __floats2half2_rn(x.x, x.y);
        p[1] = __floats2half2_rn(x.z, x.w);
        __half2* q = (__half2*)(hh + base) + tid * 2;
        q[0] = __floats2half2_rn(c.x, c.y);
        q[1] = __floats2half2_rn(c.z, c.w);
    }

    float s = x.x + x.y + x.z + x.w;
    s = block_sum256(s);
    const float mu = s * (1.0f / HDIM);

    float d0 = x.x - mu, d1 = x.y - mu, d2 = x.z - mu, d3 = x.w - mu;
    float sq = d0 * d0 + d1 * d1 + d2 * d2 + d3 * d3;
    sq = block_sum256(sq);
    const float rstd = rsqrtf(sq * (1.0f / HDIM) + 1e-12f);

    float4 g4 = ((const float4*)gamma)[tid];
    float4 b4 = ((const float4*)beta)[tid];
    float o0 = d0 * rstd * g4.x + b4.x;
    float o1 = d1 * rstd * g4.y + b4.y;
    float o2 = d2 * rstd * g4.z + b4.z;
    float o3 = d3 * rstd * g4.w + b4.w;
    if (OUTHALF) {
        __half2* p = (__half2*)((__half*)out + base) + tid * 2;
        p[0] = __floats2half2_rn(o0, o1);
        p[1] = __floats2half2_rn(o2, o3);
    } else {
        ((float4*)((float*)out + base))[tid] = make_float4(o0, o1, o2, o3);
    }
}

// ---------------------------------------------------------------------------
// convA: fp16-convert hs ONLY (dense_w moved to prepB on the side stream)
// ---------------------------------------------------------------------------
#define CA0 (NTOK * IDIM / 4)
__global__ void convA_kernel(const float* __restrict__ hs, __half* __restrict__ hsh)
{
    int i = blockIdx.x * blockDim.x + threadIdx.x;
    if (i >= CA0) return;
    float4 v = *(const float4*)(hs + (size_t)i * 4);
    __half2* o = (__half2*)(hsh + (size_t)i * 4);
    o[0] = __floats2half2_rn(v.x, v.y);
    o[1] = __floats2half2_rn(v.z, v.w);
}

// ---------------------------------------------------------------------------
// prepB: all weights (side stream). Segments:
//  0: dw  = h(dense_w)            [H*I]
//  1: dnw = h(down_w)             [TD*H]
//  2: vw  = h(value_w)            [H*H]
//  3: qwT[n,k] = h(query_w[k,n])  [H*H]
//  4: kwT[n,k] = h(key_w[k,n])    [H*H]
//  5: uw2e[j,h]                   [TDBP*H]
// ---------------------------------------------------------------------------
#define PBW (HDIM * IDIM)
#define PB0 (TD * HDIM)
#define PB1 (HDIM * HDIM)
#define PB4 (TDBP * HDIM)
#define PB_TOTAL (PBW + PB0 + 3 * PB1 + PB4)

__global__ void prepB_kernel(
    const float* __restrict__ dense_w,
    const float* __restrict__ down_w, const float* __restrict__ value_w,
    const float* __restrict__ query_w, const float* __restrict__ key_w,
    const float* __restrict__ up_w,   const float* __restrict__ up_b,
    __half* __restrict__ dw,
    __half* __restrict__ dnw, __half* __restrict__ vw,
    __half* __restrict__ qwT, __half* __restrict__ kwT,
    __half* __restrict__ uw2e)
{
    int idx = blockIdx.x * blockDim.x + threadIdx.x;
    if (idx < PBW) { dw[idx] = __float2half_rn(dense_w[idx]); return; }
    idx -= PBW;
    if (idx < PB0) { dnw[idx] = __float2half_rn(down_w[idx]); return; }
    idx -= PB0;
    if (idx < PB1) { vw[idx] = __float2half_rn(value_w[idx]); return; }
    idx -= PB1;
    if (idx < PB1) {
        int n = idx >> 10, k = idx & (HDIM - 1);
        qwT[idx] = __float2half_rn(query_w[(size_t)k * HDIM + n]);
        return;
    }
    idx -= PB1;
    if (idx < PB1) {
        int n = idx >> 10, k = idx & (HDIM - 1);
        kwT[idx] = __float2half_rn(key_w[(size_t)k * HDIM + n]);
        return;
    }
    idx -= PB1;
    if (idx < PB4) {
        int j = idx >> 10, h = idx & (HDIM - 1);
        float v = 0.0f;
        if (j < TD) {
            int t = j >> 6, d = j & 63;
            v = up_w[((size_t)t * HDIM + h) * 64 + d];
        } else if (j < TD + TTASK) {
            v = up_b[(size_t)(j - TD) * HDIM + h];
        }
        uw2e[idx] = __float2half_rn(v);
    }
}

// qkb[k] = sum_j query_b[j] * key_w[j,k]
__global__ void qkb_kernel(const float* __restrict__ qb,
                           const float* __restrict__ kw,
                           float* __restrict__ qkb)
{
    int k = blockIdx.x * blockDim.x + threadIdx.x;
    if (k >= HDIM) return;
    float s = 0.f;
    #pragma unroll 8
    for (int j = 0; j < HDIM; j++) s += qb[j] * kw[(size_t)j * HDIM + k];
    qkb[k] = s;
}

// ---------------------------------------------------------------------------
// Scores + softmax over tasks + pdr (fp16, stride TDBP, pad zeroed)
// ---------------------------------------------------------------------------
__global__ void __launch_bounds__(256) score_softmax_kernel(
    const __half* __restrict__ dr, const __half* __restrict__ e,
    const __half* __restrict__ qk, const float* __restrict__ up_b,
    __half* __restrict__ pdr)
{
    const int n = blockIdx.x;
    const int tid = threadIdx.x;
    const int w = tid >> 5, l = tid & 31;

    const size_t b512 = (size_t)n * TD;
    float v = __half2float(dr[b512 + w * 64 + l])      * __half2float(e[b512 + w * 64 + l])
            + __half2float(dr[b512 + w * 64 + 32 + l]) * __half2float(e[b512 + w * 64 + 32 + l]);

    const __half* qrow = qk + (size_t)n * HDIM;
    const float* ub = up_b + (size_t)w * HDIM;
    float u = 0.f;
    #pragma unroll 8
    for (int h = l; h < HDIM; h += 32) u += __half2float(qrow[h]) * ub[h];
    v += u;

    #pragma unroll
    for (int o = 16; o > 0; o >>= 1) v += __shfl_xor_sync(0xffffffffu, v, o);

    __shared__ float s[TTASK];
    if (l == 0) s[w] = v;
    __syncthreads();

    float mx = s[0];
    #pragma unroll
    for (int t = 1; t < TTASK; t++) mx = fmaxf(mx, s[t]);
    float p[TTASK]; float sum = 0.f;
    #pragma unroll
    for (int t = 0; t < TTASK; t++) { p[t] = __expf(s[t] - mx); sum += p[t]; }
    const float inv = 1.0f / sum;

    const size_t b = (size_t)n * TDBP;
    #pragma unroll
    for (int r = 0; r < 2; r++) {
        int c = tid + r * 256;
        int t = c >> 6;
        pdr[b + c] = __float2half_rn(p[t] * inv * __half2float(dr[b512 + c]));
    }
    if (tid < TTASK) pdr[b + TD + tid] = __float2half_rn(p[tid] * inv);
    if (tid < TDBP - TD - TTASK) pdr[b + TD + TTASK + tid] = __float2half_rn(0.0f);
}

// ---------------------------------------------------------------------------
// Launch
// ---------------------------------------------------------------------------
struct Scratch {
    __half *hsh, *hh, *pre, *ain, *dr, *qk, *e, *pdr;
    __half *dw, *dnw, *qwT, *kwT, *wqk, *vw, *uw2e, *w2;
    float *h, *hv, *qkb;
    cudaStream_t s1;
    cudaEvent_t evFork, evPrep, evWqk, evLN, evDr, evHv;
};

static constexpr int SMEM_128 = 3 * 2 * 16384;           // 98304 B
static constexpr int SMEM_64  = 3 * (8192 + 16384);      // 73728 B

static Scratch init_once()
{
    Scratch s;
    cudaGetSymbolAddress((void**)&s.hsh,  g_hsh);
    cudaGetSymbolAddress((void**)&s.hh,   g_hh);
    cudaGetSymbolAddress((void**)&s.pre,  g_pre);
    cudaGetSymbolAddress((void**)&s.ain,  g_ain);
    cudaGetSymbolAddress((void**)&s.dr,   g_dr);
    cudaGetSymbolAddress((void**)&s.qk,   g_qk);
    cudaGetSymbolAddress((void**)&s.e,    g_e);
    cudaGetSymbolAddress((void**)&s.pdr,  g_pdr);
    cudaGetSymbolAddress((void**)&s.dw,   g_dw);
    cudaGetSymbolAddress((void**)&s.dnw,  g_dnw);
    cudaGetSymbolAddress((void**)&s.qwT,  g_qwT);
    cudaGetSymbolAddress((void**)&s.kwT,  g_kwT);
    cudaGetSymbolAddress((void**)&s.wqk,  g_wqk);
    cudaGetSymbolAddress((void**)&s.vw,   g_vw);
    cudaGetSymbolAddress((void**)&s.uw2e, g_uw2e);
    cudaGetSymbolAddress((void**)&s.w2,   g_w2);
    cudaGetSymbolAddress((void**)&s.h,    g_h);
    cudaGetSymbolAddress((void**)&s.hv,   g_hv);
    cudaGetSymbolAddress((void**)&s.qkb,  g_qkb);
    cudaFuncSetAttribute(gemm_h<128, true,  false, false, false>, cudaFuncAttributeMaxDynamicSharedMemorySize, SMEM_128);
    cudaFuncSetAttribute(gemm_h<128, true,  false, false, true >, cudaFuncAttributeMaxDynamicSharedMemorySize, SMEM_128);
    cudaFuncSetAttribute(gemm_h<128, false, false, false, false>, cudaFuncAttributeMaxDynamicSharedMemorySize, SMEM_128);
    cudaFuncSetAttribute(gemm_h<128, false, false, true,  false>, cudaFuncAttributeMaxDynamicSharedMemorySize, SMEM_128);
    cudaFuncSetAttribute(gemm_h<64,  true,  true,  false, true >, cudaFuncAttributeMaxDynamicSharedMemorySize, SMEM_64);
    cudaFuncSetAttribute(gemm_h<64,  false, false, false, true >, cudaFuncAttributeMaxDynamicSharedMemorySize, SMEM_64);
    cudaStreamCreateWithFlags(&s.s1, cudaStreamNonBlocking);
    cudaEventCreateWithFlags(&s.evFork, cudaEventDisableTiming);
    cudaEventCreateWithFlags(&s.evPrep, cudaEventDisableTiming);
    cudaEventCreateWithFlags(&s.evWqk,  cudaEventDisableTiming);
    cudaEventCreateWithFlags(&s.evLN,   cudaEventDisableTiming);
    cudaEventCreateWithFlags(&s.evDr,   cudaEventDisableTiming);
    cudaEventCreateWithFlags(&s.evHv,   cudaEventDisableTiming);
    return s;
}

extern "C" void kernel_launch(void* const* d_in, const int* in_sizes, int n_in,
                              void* d_out, int out_size)
{
    const float* hs      = (const float*)d_in[0];
    const float* inp     = (const float*)d_in[1];
    const float* dense_w = (const float*)d_in[2];
    const float* dense_b = (const float*)d_in[3];
    const float* ln_g    = (const float*)d_in[4];
    const float* ln_b    = (const float*)d_in[5];
    const float* down_w  = (const float*)d_in[6];
    const float* down_b  = (const float*)d_in[7];
    const float* up_w    = (const float*)d_in[8];
    const float* up_b    = (const float*)d_in[9];
    const float* key_w   = (const float*)d_in[10];  // key_b cancels in softmax
    const float* query_w = (const float*)d_in[12];
    const float* query_b = (const float*)d_in[13];
    const float* value_w = (const float*)d_in[14];
    float* out = (float*)d_out;

    static Scratch s = init_once();
    cudaStream_t s0 = 0, s1 = s.s1;
    dim3 blk(256);

    // ---- fork: s1 branches off s0 ----
    cudaEventRecord(s.evFork, s0);
    cudaStreamWaitEvent(s1, s.evFork, 0);

    // s1: all weight prep (incl. dense_w) -> qkb -> wqk -> W2
    prepB_kernel<<<(PB_TOTAL + 255) / 256, blk, 0, s1>>>(
        dense_w, down_w, value_w, query_w, key_w, up_w, up_b,
        s.dw, s.dnw, s.vw, s.qwT, s.kwT, s.uw2e);
    cudaEventRecord(s.evPrep, s1);
    qkb_kernel<<<HDIM / 256, blk, 0, s1>>>(query_b, key_w, s.qkb);
    // W_qk[k,i] = sum_j Kw[j,k] Qw[j,i]  (= kwT @ qwT^T)   [1024,1024], K=1024
    gemm_h<64, false, false, false, true><<<dim3(8, 16), blk, SMEM_64, s1>>>(
        s.kwT, s.qwT, nullptr, nullptr, s.wqk, HDIM, HDIM);
    cudaEventRecord(s.evWqk, s1);
    // W2 = value_w @ uw2e^T   [1024, 640], K=1024
    gemm_h<64, false, false, false, true><<<dim3(TDBP / 128, 16), blk, SMEM_64, s1>>>(
        s.vw, s.uw2e, nullptr, nullptr, s.w2, TDBP, HDIM);

    // s0: hs conversion, then dense (needs dw from prepB) + LN1
    convA_kernel<<<(CA0 + 255) / 256, blk, 0, s0>>>(hs, s.hsh);
    cudaStreamWaitEvent(s0, s.evPrep, 0);
    // h = hs @ dense_w^T + dense_b            [4096,1024], K=4096 (fp32 out)
    gemm_h<128, true, false, false, false><<<dim3(8, 32), blk, SMEM_128, s0>>>(
        s.hsh, s.dw, dense_b, nullptr, s.h, HDIM, IDIM);
    // pre = h16(inp + h); ain = h16(LN(.)); hh = h16(h)
    add_ln_kernel<true, true><<<NTOK, blk, 0, s0>>>(inp, s.h, ln_g, ln_b, s.pre, s.hh, s.ain);
    cudaEventRecord(s.evLN, s0);

    // s1 (after LN): dr (gates score), then hv (gates fus only)
    cudaStreamWaitEvent(s1, s.evLN, 0);
    // dr = relu(ain @ down_w^T + down_b)      [4096,512], K=1024
    gemm_h<64, true, true, false, true><<<dim3(4, 64), blk, SMEM_64, s1>>>(
        s.ain, s.dnw, down_b, nullptr, s.dr, TD, HDIM);
    cudaEventRecord(s.evDr, s1);
    // hv = hh @ value_w^T                     [4096,1024], K=1024 (fp32 out)
    gemm_h<128, false, false, false, false><<<dim3(8, 32), blk, SMEM_128, s1>>>(
        s.hh, s.vw, nullptr, nullptr, s.hv, HDIM, HDIM);
    cudaEventRecord(s.evHv, s1);

    // s0: qk -> e -> (wait dr) -> score -> (wait hv) -> fus -> LN2
    cudaStreamWaitEvent(s0, s.evWqk, 0);
    // qk = pre @ W_qk^T + qkb                 [4096,1024], K=1024
    gemm_h<128, true, false, false, true><<<dim3(8, 32), blk, SMEM_128, s0>>>(
        s.pre, s.wqk, s.qkb, nullptr, s.qk, HDIM, HDIM);
    // e = qk @ uw2e[0:512]^T                  [4096,512], K=1024
    gemm_h<64, false, false, false, true><<<dim3(4, 64), blk, SMEM_64, s0>>>(
        s.qk, s.uw2e, nullptr, nullptr, s.e, TD, HDIM);
    cudaStreamWaitEvent(s0, s.evDr, 0);
    // scores + softmax + pdr
    score_softmax_kernel<<<NTOK, blk, 0, s0>>>(s.dr, s.e, s.qk, up_b, s.pdr);
    cudaStreamWaitEvent(s0, s.evHv, 0);   // hv (and earlier W2) ready
    // fus = pdr @ W2^T + hv                   [4096,1024], K=640 (fp32 out -> g_h)
    gemm_h<128, false, false, true, false><<<dim3(8, 32), blk, SMEM_128, s0>>>(
        s.pdr, s.w2, nullptr, s.hv, s.h, HDIM, TDBP);
    // out = LN(inp + fus)
    add_ln_kernel<false, false><<<NTOK, blk, 0, s0>>>(inp, s.h, ln_g, ln_b, nullptr, nullptr, out);
}

// round 16
// speedup vs baseline: 2.2837x; 1.0458x over previous
#include <cuda_runtime.h>
#include <cuda_fp16.h>
#include <stdint.h>

// ---------------------------------------------------------------------------
// Problem constants
// ---------------------------------------------------------------------------
#define NTOK 4096          // B*S
#define HDIM 1024          // hidden
#define IDIM 4096          // intermediate
#define TTASK 8            // tasks
#define TD 512             // T*D
#define TDBP 640           // T*D + T, padded to multiple of 128

// ---------------------------------------------------------------------------
// Scratch (static device globals; no allocation allowed)
// ---------------------------------------------------------------------------
__device__ __align__(16) __half g_hsh[NTOK * IDIM];   // hs in fp16
__device__ float  g_h  [NTOK * HDIM];                 // dense out (fp32); later reused for fus
__device__ __align__(16) __half g_hh [NTOK * HDIM];   // h in fp16
__device__ __align__(16) __half g_pre[NTOK * HDIM];
__device__ __align__(16) __half g_ain[NTOK * HDIM];
__device__ __align__(16) __half g_dr [NTOK * TD];
__device__ __align__(16) __half g_qk [NTOK * HDIM];
__device__ __align__(16) __half g_e  [NTOK * TD];
__device__ __align__(16) __half g_pdr[NTOK * TDBP];
__device__ float  g_hv [NTOK * HDIM];                 // h @ value_w^T (fp32)
// fp16 weights, all [N, K] row-major
__device__ __align__(16) __half g_dw  [HDIM * IDIM];  // dense_w
__device__ __align__(16) __half g_dnw [TD * HDIM];    // down_w
__device__ __align__(16) __half g_qwT [HDIM * HDIM];  // query_w^T
__device__ __align__(16) __half g_kwT [HDIM * HDIM];  // key_w^T
__device__ __align__(16) __half g_wqk [HDIM * HDIM];  // W_qk = Qw^T Kw
__device__ __align__(16) __half g_vw  [HDIM * HDIM];  // value_w
__device__ __align__(16) __half g_uw2e[TDBP * HDIM];  // rows j<512: up_w[t,h,d]; 512..519: up_b; else 0
__device__ __align__(16) __half g_w2  [HDIM * TDBP];  // W2 = value_w @ uw2e^T  [n][j]
__device__ float g_qkb[HDIM];                         // query_b @ key_w

// ---------------------------------------------------------------------------
// PTX helpers
// ---------------------------------------------------------------------------
__device__ __forceinline__ uint32_t smem_u32(const void* p) {
    uint32_t a;
    asm("{ .reg .u64 t; cvta.to.shared.u64 t, %1; cvt.u32.u64 %0, t; }" : "=r"(a) : "l"(p));
    return a;
}
__device__ __forceinline__ void cp_async16(uint32_t smem, const void* gmem) {
    asm volatile("cp.async.cg.shared.global [%0], [%1], 16;\n" :: "r"(smem), "l"(gmem));
}
__device__ __forceinline__ void cp_commit() {
    asm volatile("cp.async.commit_group;\n");
}
template<int W> __device__ __forceinline__ void cp_wait() {
    asm volatile("cp.async.wait_group %0;\n" :: "n"(W));
}
__device__ __forceinline__ uint32_t sw128(uint32_t off) {   // SW128 swizzle
    return off ^ ((off >> 3) & 0x70);
}
__device__ __forceinline__ void ldsm4(uint32_t* d, uint32_t addr) {
    asm volatile("ldmatrix.sync.aligned.m8n8.x4.shared.b16 {%0,%1,%2,%3}, [%4];"
        : "=r"(d[0]), "=r"(d[1]), "=r"(d[2]), "=r"(d[3]) : "r"(addr));
}
__device__ __forceinline__ void mma_f16(float* c, const uint32_t* a, const uint32_t* b) {
    asm volatile("mma.sync.aligned.m16n8k16.row.col.f32.f16.f16.f32 "
        "{%0,%1,%2,%3}, {%4,%5,%6,%7}, {%8,%9}, {%0,%1,%2,%3};"
        : "+f"(c[0]), "+f"(c[1]), "+f"(c[2]), "+f"(c[3])
        : "r"(a[0]), "r"(a[1]), "r"(a[2]), "r"(a[3]), "r"(b[0]), "r"(b[1]));
}

// ---------------------------------------------------------------------------
// fp16 HMMA GEMM: C[M,N] = A[M,K](fp16) @ B[N,K](fp16)^T (+bias)(relu)(+C2)
// CTA tile MT x 128, BK=64 halfs (128B SW128 rows), 256 thr, 8 warps (2x4),
// 3-stage cp.async, single barrier per K-iter, fp32 accum, 2 CTAs/SM.
// Requires M%MT==0, N%128==0, K%64==0, K/64 >= 3.
// ---------------------------------------------------------------------------
template<int MT, bool HASBIAS, bool RELU, bool ADDC, bool OUTHALF>
__global__ void __launch_bounds__(256, 2) gemm_h(
    const __half* __restrict__ A, const __half* __restrict__ B,
    const float* __restrict__ bias, const float* __restrict__ C2,
    void* __restrict__ Cv, int N, int K)
{
    constexpr int ASTG = MT * 128;              // bytes per A stage
    constexpr int BSTG = 128 * 128;             // bytes per B stage
    constexpr int MI = MT / 32;                 // 16-row m-subtiles per warp
    extern __shared__ __align__(1024) char smem[];
    const uint32_t sb  = smem_u32(smem);
    const uint32_t SA  = sb;
    const uint32_t SBB = sb + 3 * ASTG;

    const int tid = threadIdx.x, w = tid >> 5, lane = tid & 31;
    const int m0 = blockIdx.y * MT, n0 = blockIdx.x * 128;
    const int wm = (w & 1) * (MT / 2), wn = (w >> 1) * 32;
    const int qr = lane >> 2, qc = lane & 3;
    const int nt = K >> 6;

    auto copy_stage = [&](int s, int k0 /*halfs*/) {
        #pragma unroll
        for (int i = 0; i < MT / 32; i++) {
            int g = tid + 256 * i;
            int r = g >> 3, cb = (g & 7) << 4;
            cp_async16(SA + s * ASTG + sw128(r * 128 + cb),
                       A + (size_t)(m0 + r) * K + k0 + (cb >> 1));
        }
        #pragma unroll
        for (int i = 0; i < 4; i++) {
            int g = tid + 256 * i;
            int r = g >> 3, cb = (g & 7) << 4;
            cp_async16(SBB + s * BSTG + sw128(r * 128 + cb),
                       B + (size_t)(n0 + r) * K + k0 + (cb >> 1));
        }
    };

    float acc[MI][4][4];
    #pragma unroll
    for (int mi = 0; mi < MI; mi++)
        #pragma unroll
        for (int nj = 0; nj < 4; nj++)
            #pragma unroll
            for (int r = 0; r < 4; r++) acc[mi][nj][r] = 0.0f;

    copy_stage(0, 0);   cp_commit();
    copy_stage(1, 64);  cp_commit();

    const int a_r  = lane & 15;
    const int a_cb = (lane >> 4) << 4;            // 0 | 16
    const int b_r  = ((lane >> 4) & 1) * 8 + (lane & 7);
    const int b_cb = ((lane >> 3) & 1) << 4;      // 0 | 16

    for (int t = 0; t < nt; t++) {
        cp_wait<1>();
        __syncthreads();

        const int nxt = t + 2;
        if (nxt < nt) copy_stage(nxt % 3, nxt * 64);
        cp_commit();

        const uint32_t aB = SA  + (t % 3) * ASTG;
        const uint32_t bB = SBB + (t % 3) * BSTG;

        #pragma unroll
        for (int kc = 0; kc < 4; kc++) {
            const int kb = kc * 32;               // byte col base (16 halfs)
            uint32_t bf[8];
            #pragma unroll
            for (int h = 0; h < 2; h++) {
                int r = wn + h * 16 + b_r;
                ldsm4(&bf[h * 4], bB + sw128(r * 128 + kb + b_cb));
            }
            #pragma unroll
            for (int mi = 0; mi < MI; mi++) {
                int r = wm + mi * 16 + a_r;
                uint32_t af[4];
                ldsm4(af, aB + sw128(r * 128 + kb + a_cb));
                #pragma unroll
                for (int nj = 0; nj < 4; nj++)
                    mma_f16(acc[mi][nj], af, &bf[nj * 2]);
            }
        }
    }

    // ----- epilogue -----
    float2 bv[4];
    if (HASBIAS) {
        #pragma unroll
        for (int nj = 0; nj < 4; nj++)
            bv[nj] = *(const float2*)&bias[n0 + wn + nj * 8 + qc * 2];
    }
    #pragma unroll
    for (int mi = 0; mi < MI; mi++) {
        const int r0 = m0 + wm + mi * 16 + qr;
        #pragma unroll
        for (int nj = 0; nj < 4; nj++) {
            const int cc = n0 + wn + nj * 8 + qc * 2;
            float2 v0 = make_float2(acc[mi][nj][0], acc[mi][nj][1]);
            float2 v1 = make_float2(acc[mi][nj][2], acc[mi][nj][3]);
            if (HASBIAS) {
                v0.x += bv[nj].x; v0.y += bv[nj].y;
                v1.x += bv[nj].x; v1.y += bv[nj].y;
            }
            if (ADDC) {
                float2 c0 = *(const float2*)&C2[(size_t)r0 * N + cc];
                float2 c1 = *(const float2*)&C2[(size_t)(r0 + 8) * N + cc];
                v0.x += c0.x; v0.y += c0.y;
                v1.x += c1.x; v1.y += c1.y;
            }
            if (RELU) {
                v0.x = fmaxf(v0.x, 0.f); v0.y = fmaxf(v0.y, 0.f);
                v1.x = fmaxf(v1.x, 0.f); v1.y = fmaxf(v1.y, 0.f);
            }
            if (OUTHALF) {
                __half* C = (__half*)Cv;
                *(__half2*)&C[(size_t)r0 * N + cc]       = __floats2half2_rn(v0.x, v0.y);
                *(__half2*)&C[(size_t)(r0 + 8) * N + cc] = __floats2half2_rn(v1.x, v1.y);
            } else {
                float* C = (float*)Cv;
                *(float2*)&C[(size_t)r0 * N + cc]       = v0;
                *(float2*)&C[(size_t)(r0 + 8) * N + cc] = v1;
            }
        }
    }
}

// ---------------------------------------------------------------------------
// Block reduction (256 threads)
// ---------------------------------------------------------------------------
__device__ __forceinline__ float block_sum256(float v)
{
    __shared__ float buf[8];
    int lane = threadIdx.x & 31, wid = threadIdx.x >> 5;
    #pragma unroll
    for (int o = 16; o > 0; o >>= 1) v += __shfl_xor_sync(0xffffffffu, v, o);
    if (lane == 0) buf[wid] = v;
    __syncthreads();
    float r = buf[0] + buf[1] + buf[2] + buf[3] + buf[4] + buf[5] + buf[6] + buf[7];
    __syncthreads();
    return r;
}

// ---------------------------------------------------------------------------
// add + LayerNorm: x = x1 + x2; optionally write fp16 x AND fp16 x2;
// out = LN(x) (fp16|fp32)
// ---------------------------------------------------------------------------
template<bool WRITE_PRE, bool OUTHALF>
__global__ void __launch_bounds__(256) add_ln_kernel(
    const float* __restrict__ x1, const float* __restrict__ x2,
    const float* __restrict__ gamma, const float* __restrict__ beta,
    __half* __restrict__ pre, __half* __restrict__ hh, void* __restrict__ out)
{
    const int n = blockIdx.x;
    const int tid = threadIdx.x;
    const size_t base = (size_t)n * HDIM;

    float4 a = ((const float4*)(x1 + base))[tid];
    float4 c = ((const float4*)(x2 + base))[tid];
    float4 x = make_float4(a.x + c.x, a.y + c.y, a.z + c.z, a.w + c.w);
    if (WRITE_PRE) {
        __half2* p = (__half2*)(pre + base) + tid * 2;
        p[0] = __floats2half2_rn(x.x, x.y);
        p[1] = __floats2half2_rn(x.z, x.w);
        __half2* q = (__half2*)(hh + base) + tid * 2;
        q[0] = __floats2half2_rn(c.x, c.y);
        q[1] = __floats2half2_rn(c.z, c.w);
    }

    float s = x.x + x.y + x.z + x.w;
    s = block_sum256(s);
    const float mu = s * (1.0f / HDIM);

    float d0 = x.x - mu, d1 = x.y - mu, d2 = x.z - mu, d3 = x.w - mu;
    float sq = d0 * d0 + d1 * d1 + d2 * d2 + d3 * d3;
    sq = block_sum256(sq);
    const float rstd = rsqrtf(sq * (1.0f / HDIM) + 1e-12f);

    float4 g4 = ((const float4*)gamma)[tid];
    float4 b4 = ((const float4*)beta)[tid];
    float o0 = d0 * rstd * g4.x + b4.x;
    float o1 = d1 * rstd * g4.y + b4.y;
    float o2 = d2 * rstd * g4.z + b4.z;
    float o3 = d3 * rstd * g4.w + b4.w;
    if (OUTHALF) {
        __half2* p = (__half2*)((__half*)out + base) + tid * 2;
        p[0] = __floats2half2_rn(o0, o1);
        p[1] = __floats2half2_rn(o2, o3);
    } else {
        ((float4*)((float*)out + base))[tid] = make_float4(o0, o1, o2, o3);
    }
}

// ---------------------------------------------------------------------------
// High-MLP fp32->fp16 converters. Each thread does 4 INDEPENDENT float4
// loads (grid-stride spacing) so DRAM latency is overlapped (MLP_eff~4).
// Grids chosen so count = gridDim*blockDim*4 exactly (no bounds checks).
// ---------------------------------------------------------------------------
#define CA0 (NTOK * IDIM / 4)   // 4194304 float4's  -> grid 4096
#define CW0 (HDIM * IDIM / 4)   // 1048576 float4's  -> grid 1024

__global__ void convA_kernel(const float* __restrict__ hs, __half* __restrict__ hsh)
{
    const int i0 = blockIdx.x * blockDim.x + threadIdx.x;
    const int stride = gridDim.x * blockDim.x;
    float4 v[4];
    #pragma unroll
    for (int k = 0; k < 4; k++)
        v[k] = *(const float4*)(hs + (size_t)(i0 + k * stride) * 4);
    #pragma unroll
    for (int k = 0; k < 4; k++) {
        __half2* o = (__half2*)(hsh + (size_t)(i0 + k * stride) * 4);
        o[0] = __floats2half2_rn(v[k].x, v[k].y);
        o[1] = __floats2half2_rn(v[k].z, v[k].w);
    }
}

__global__ void convW_kernel(const float* __restrict__ wsrc, __half* __restrict__ wdst)
{
    const int i0 = blockIdx.x * blockDim.x + threadIdx.x;
    const int stride = gridDim.x * blockDim.x;
    float4 v[4];
    #pragma unroll
    for (int k = 0; k < 4; k++)
        v[k] = *(const float4*)(wsrc + (size_t)(i0 + k * stride) * 4);
    #pragma unroll
    for (int k = 0; k < 4; k++) {
        __half2* o = (__half2*)(wdst + (size_t)(i0 + k * stride) * 4);
        o[0] = __floats2half2_rn(v[k].x, v[k].y);
        o[1] = __floats2half2_rn(v[k].z, v[k].w);
    }
}

// ---------------------------------------------------------------------------
// prepB: non-dense weights (side stream). Segments:
//  0: dnw = h(down_w)             [TD*H]
//  1: vw  = h(value_w)            [H*H]
//  2: qwT[n,k] = h(query_w[k,n])  [H*H]
//  3: kwT[n,k] = h(key_w[k,n])    [H*H]
//  4: uw2e[j,h]                   [TDBP*H]
// ---------------------------------------------------------------------------
#define PB0 (TD * HDIM)
#define PB1 (HDIM * HDIM)
#define PB4 (TDBP * HDIM)
#define PB_TOTAL (PB0 + 3 * PB1 + PB4)

__global__ void prepB_kernel(
    const float* __restrict__ down_w, const float* __restrict__ value_w,
    const float* __restrict__ query_w, const float* __restrict__ key_w,
    const float* __restrict__ up_w,   const float* __restrict__ up_b,
    __half* __restrict__ dnw, __half* __restrict__ vw,
    __half* __restrict__ qwT, __half* __restrict__ kwT,
    __half* __restrict__ uw2e)
{
    int idx = blockIdx.x * blockDim.x + threadIdx.x;
    if (idx < PB0) { dnw[idx] = __float2half_rn(down_w[idx]); return; }
    idx -= PB0;
    if (idx < PB1) { vw[idx] = __float2half_rn(value_w[idx]); return; }
    idx -= PB1;
    if (idx < PB1) {
        int n = idx >> 10, k = idx & (HDIM - 1);
        qwT[idx] = __float2half_rn(query_w[(size_t)k * HDIM + n]);
        return;
    }
    idx -= PB1;
    if (idx < PB1) {
        int n = idx >> 10, k = idx & (HDIM - 1);
        kwT[idx] = __float2half_rn(key_w[(size_t)k * HDIM + n]);
        return;
    }
    idx -= PB1;
    if (idx < PB4) {
        int j = idx >> 10, h = idx & (HDIM - 1);
        float v = 0.0f;
        if (j < TD) {
            int t = j >> 6, d = j & 63;
            v = up_w[((size_t)t * HDIM + h) * 64 + d];
        } else if (j < TD + TTASK) {
            v = up_b[(size_t)(j - TD) * HDIM + h];
        }
        uw2e[idx] = __float2half_rn(v);
    }
}

// qkb[k] = sum_j query_b[j] * key_w[j,k]
__global__ void qkb_kernel(const float* __restrict__ qb,
                           const float* __restrict__ kw,
                           float* __restrict__ qkb)
{
    int k = blockIdx.x * blockDim.x + threadIdx.x;
    if (k >= HDIM) return;
    float s = 0.f;
    #pragma unroll 8
    for (int j = 0; j < HDIM; j++) s += qb[j] * kw[(size_t)j * HDIM + k];
    qkb[k] = s;
}

// ---------------------------------------------------------------------------
// Scores + softmax over tasks + pdr (fp16, stride TDBP, pad zeroed)
// ---------------------------------------------------------------------------
__global__ void __launch_bounds__(256) score_softmax_kernel(
    const __half* __restrict__ dr, const __half* __restrict__ e,
    const __half* __restrict__ qk, const float* __restrict__ up_b,
    __half* __restrict__ pdr)
{
    const int n = blockIdx.x;
    const int tid = threadIdx.x;
    const int w = tid >> 5, l = tid & 31;

    const size_t b512 = (size_t)n * TD;
    float v = __half2float(dr[b512 + w * 64 + l])      * __half2float(e[b512 + w * 64 + l])
            + __half2float(dr[b512 + w * 64 + 32 + l]) * __half2float(e[b512 + w * 64 + 32 + l]);

    const __half* qrow = qk + (size_t)n * HDIM;
    const float* ub = up_b + (size_t)w * HDIM;
    float u = 0.f;
    #pragma unroll 8
    for (int h = l; h < HDIM; h += 32) u += __half2float(qrow[h]) * ub[h];
    v += u;

    #pragma unroll
    for (int o = 16; o > 0; o >>= 1) v += __shfl_xor_sync(0xffffffffu, v, o);

    __shared__ float s[TTASK];
    if (l == 0) s[w] = v;
    __syncthreads();

    float mx = s[0];
    #pragma unroll
    for (int t = 1; t < TTASK; t++) mx = fmaxf(mx, s[t]);
    float p[TTASK]; float sum = 0.f;
    #pragma unroll
    for (int t = 0; t < TTASK; t++) { p[t] = __expf(s[t] - mx); sum += p[t]; }
    const float inv = 1.0f / sum;

    const size_t b = (size_t)n * TDBP;
    #pragma unroll
    for (int r = 0; r < 2; r++) {
        int c = tid + r * 256;
        int t = c >> 6;
        pdr[b + c] = __float2half_rn(p[t] * inv * __half2float(dr[b512 + c]));
    }
    if (tid < TTASK) pdr[b + TD + tid] = __float2half_rn(p[tid] * inv);
    if (tid < TDBP - TD - TTASK) pdr[b + TD + TTASK + tid] = __float2half_rn(0.0f);
}

// ---------------------------------------------------------------------------
// Launch
// ---------------------------------------------------------------------------
struct Scratch {
    __half *hsh, *hh, *pre, *ain, *dr, *qk, *e, *pdr;
    __half *dw, *dnw, *qwT, *kwT, *wqk, *vw, *uw2e, *w2;
    float *h, *hv, *qkb;
    cudaStream_t s1;
    cudaEvent_t evFork, evDW, evWqk, evLN, evDr, evHv;
};

static constexpr int SMEM_128 = 3 * 2 * 16384;           // 98304 B
static constexpr int SMEM_64  = 3 * (8192 + 16384);      // 73728 B

static Scratch init_once()
{
    Scratch s;
    cudaGetSymbolAddress((void**)&s.hsh,  g_hsh);
    cudaGetSymbolAddress((void**)&s.hh,   g_hh);
    cudaGetSymbolAddress((void**)&s.pre,  g_pre);
    cudaGetSymbolAddress((void**)&s.ain,  g_ain);
    cudaGetSymbolAddress((void**)&s.dr,   g_dr);
    cudaGetSymbolAddress((void**)&s.qk,   g_qk);
    cudaGetSymbolAddress((void**)&s.e,    g_e);
    cudaGetSymbolAddress((void**)&s.pdr,  g_pdr);
    cudaGetSymbolAddress((void**)&s.dw,   g_dw);
    cudaGetSymbolAddress((void**)&s.dnw,  g_dnw);
    cudaGetSymbolAddress((void**)&s.qwT,  g_qwT);
    cudaGetSymbolAddress((void**)&s.kwT,  g_kwT);
    cudaGetSymbolAddress((void**)&s.wqk,  g_wqk);
    cudaGetSymbolAddress((void**)&s.vw,   g_vw);
    cudaGetSymbolAddress((void**)&s.uw2e, g_uw2e);
    cudaGetSymbolAddress((void**)&s.w2,   g_w2);
    cudaGetSymbolAddress((void**)&s.h,    g_h);
    cudaGetSymbolAddress((void**)&s.hv,   g_hv);
    cudaGetSymbolAddress((void**)&s.qkb,  g_qkb);
    cudaFuncSetAttribute(gemm_h<128, true,  false, false, false>, cudaFuncAttributeMaxDynamicSharedMemorySize, SMEM_128);
    cudaFuncSetAttribute(gemm_h<128, true,  false, false, true >, cudaFuncAttributeMaxDynamicSharedMemorySize, SMEM_128);
    cudaFuncSetAttribute(gemm_h<128, false, false, false, false>, cudaFuncAttributeMaxDynamicSharedMemorySize, SMEM_128);
    cudaFuncSetAttribute(gemm_h<128, false, false, true,  false>, cudaFuncAttributeMaxDynamicSharedMemorySize, SMEM_128);
    cudaFuncSetAttribute(gemm_h<64,  true,  true,  false, true >, cudaFuncAttributeMaxDynamicSharedMemorySize, SMEM_64);
    cudaFuncSetAttribute(gemm_h<64,  false, false, false, true >, cudaFuncAttributeMaxDynamicSharedMemorySize, SMEM_64);
    cudaStreamCreateWithFlags(&s.s1, cudaStreamNonBlocking);
    cudaEventCreateWithFlags(&s.evFork, cudaEventDisableTiming);
    cudaEventCreateWithFlags(&s.evDW,   cudaEventDisableTiming);
    cudaEventCreateWithFlags(&s.evWqk,  cudaEventDisableTiming);
    cudaEventCreateWithFlags(&s.evLN,   cudaEventDisableTiming);
    cudaEventCreateWithFlags(&s.evDr,   cudaEventDisableTiming);
    cudaEventCreateWithFlags(&s.evHv,   cudaEventDisableTiming);
    return s;
}

extern "C" void kernel_launch(void* const* d_in, const int* in_sizes, int n_in,
                              void* d_out, int out_size)
{
    const float* hs      = (const float*)d_in[0];
    const float* inp     = (const float*)d_in[1];
    const float* dense_w = (const float*)d_in[2];
    const float* dense_b = (const float*)d_in[3];
    const float* ln_g    = (const float*)d_in[4];
    const float* ln_b    = (const float*)d_in[5];
    const float* down_w  = (const float*)d_in[6];
    const float* down_b  = (const float*)d_in[7];
    const float* up_w    = (const float*)d_in[8];
    const float* up_b    = (const float*)d_in[9];
    const float* key_w   = (const float*)d_in[10];  // key_b cancels in softmax
    const float* query_w = (const float*)d_in[12];
    const float* query_b = (const float*)d_in[13];
    const float* value_w = (const float*)d_in[14];
    float* out = (float*)d_out;

    static Scratch s = init_once();
    cudaStream_t s0 = 0, s1 = s.s1;
    dim3 blk(256);

    // ---- fork: s1 branches off s0 ----
    cudaEventRecord(s.evFork, s0);
    cudaStreamWaitEvent(s1, s.evFork, 0);

    // s1: dense_w conversion FIRST (gates dense GEMM), then other prep
    convW_kernel<<<CW0 / (256 * 4), blk, 0, s1>>>(dense_w, s.dw);
    cudaEventRecord(s.evDW, s1);
    prepB_kernel<<<(PB_TOTAL + 255) / 256, blk, 0, s1>>>(
        down_w, value_w, query_w, key_w, up_w, up_b,
        s.dnw, s.vw, s.qwT, s.kwT, s.uw2e);
    qkb_kernel<<<HDIM / 256, blk, 0, s1>>>(query_b, key_w, s.qkb);
    // W_qk[k,i] = sum_j Kw[j,k] Qw[j,i]  (= kwT @ qwT^T)   [1024,1024], K=1024
    gemm_h<64, false, false, false, true><<<dim3(8, 16), blk, SMEM_64, s1>>>(
        s.kwT, s.qwT, nullptr, nullptr, s.wqk, HDIM, HDIM);
    cudaEventRecord(s.evWqk, s1);
    // W2 = value_w @ uw2e^T   [1024, 640], K=1024
    gemm_h<64, false, false, false, true><<<dim3(TDBP / 128, 16), blk, SMEM_64, s1>>>(
        s.vw, s.uw2e, nullptr, nullptr, s.w2, TDBP, HDIM);

    // s0: hs conversion (high MLP), then dense (needs dw) + LN1
    convA_kernel<<<CA0 / (256 * 4), blk, 0, s0>>>(hs, s.hsh);
    cudaStreamWaitEvent(s0, s.evDW, 0);
    // h = hs @ dense_w^T + dense_b            [4096,1024], K=4096 (fp32 out)
    gemm_h<128, true, false, false, false><<<dim3(8, 32), blk, SMEM_128, s0>>>(
        s.hsh, s.dw, dense_b, nullptr, s.h, HDIM, IDIM);
    // pre = h16(inp + h); ain = h16(LN(.)); hh = h16(h)
    add_ln_kernel<true, true><<<NTOK, blk, 0, s0>>>(inp, s.h, ln_g, ln_b, s.pre, s.hh, s.ain);
    cudaEventRecord(s.evLN, s0);

    // s1 (after LN): dr (gates score), then hv (gates fus only)
    cudaStreamWaitEvent(s1, s.evLN, 0);
    // dr = relu(ain @ down_w^T + down_b)      [4096,512], K=1024
    gemm_h<64, true, true, false, true><<<dim3(4, 64), blk, SMEM_64, s1>>>(
        s.ain, s.dnw, down_b, nullptr, s.dr, TD, HDIM);
    cudaEventRecord(s.evDr, s1);
    // hv = hh @ value_w^T                     [4096,1024], K=1024 (fp32 out)
    gemm_h<128, false, false, false, false><<<dim3(8, 32), blk, SMEM_128, s1>>>(
        s.hh, s.vw, nullptr, nullptr, s.hv, HDIM, HDIM);
    cudaEventRecord(s.evHv, s1);

    // s0: qk -> e -> (wait dr) -> score -> (wait hv) -> fus -> LN2
    cudaStreamWaitEvent(s0, s.evWqk, 0);
    // qk = pre @ W_qk^T + qkb                 [4096,1024], K=1024
    gemm_h<128, true, false, false, true><<<dim3(8, 32), blk, SMEM_128, s0>>>(
        s.pre, s.wqk, s.qkb, nullptr, s.qk, HDIM, HDIM);
    // e = qk @ uw2e[0:512]^T                  [4096,512], K=1024
    gemm_h<64, false, false, false, true><<<dim3(4, 64), blk, SMEM_64, s0>>>(
        s.qk, s.uw2e, nullptr, nullptr, s.e, TD, HDIM);
    cudaStreamWaitEvent(s0, s.evDr, 0);
    // scores + softmax + pdr
    score_softmax_kernel<<<NTOK, blk, 0, s0>>>(s.dr, s.e, s.qk, up_b, s.pdr);
    cudaStreamWaitEvent(s0, s.evHv, 0);   // hv (and earlier W2) ready
    // fus = pdr @ W2^T + hv                   [4096,1024], K=640 (fp32 out -> g_h)
    gemm_h<128, false, false, true, false><<<dim3(8, 32), blk, SMEM_128, s0>>>(
        s.pdr, s.w2, nullptr, s.hv, s.h, HDIM, TDBP);
    // out = LN(inp + fus)
    add_ln_kernel<false, false><<<NTOK, blk, 0, s0>>>(inp, s.h, ln_g, ln_b, nullptr, nullptr, out);
}